// round 9
// baseline (speedup 1.0000x reference)
#include <cuda_runtime.h>
#include <cuda_bf16.h>
#include <math.h>
#include <stdint.h>

// Problem constants
#define NB 4
#define NS 2048
#define ND 1024
#define NH 16
#define HD 64
#define NM (NB*NS)          // 8192 rows

// ---------------- scratch (device globals: no allocation allowed) ----------
__device__ float g_sin[NS*(HD/2)];
__device__ float g_cos[NS*(HD/2)];
// bf16 split buffers
__device__ __nv_bfloat16 g_q1[(size_t)NM*ND];
__device__ __nv_bfloat16 g_q2[(size_t)NM*ND];
__device__ __nv_bfloat16 g_k1[(size_t)NM*ND];
__device__ __nv_bfloat16 g_k2[(size_t)NM*ND];
__device__ __nv_bfloat16 g_v1[(size_t)NM*ND];
__device__ __nv_bfloat16 g_v2[(size_t)NM*ND];
__device__ __nv_bfloat16 g_a1[(size_t)NM*ND];
__device__ __nv_bfloat16 g_a2[(size_t)NM*ND];
__device__ __nv_bfloat16 g_b1[(size_t)3*ND*ND];
__device__ __nv_bfloat16 g_b2[(size_t)3*ND*ND];

// ---------------- helpers ----------------------------------------------------
static __device__ __forceinline__ uint32_t smem_u32(const void* p) {
    uint32_t a;
    asm("{ .reg .u64 t; cvta.to.shared.u64 t, %1; cvt.u32.u64 %0, t; }"
        : "=r"(a) : "l"(p));
    return a;
}
static __device__ __forceinline__ uint32_t packbf2(float lo, float hi) {
    __nv_bfloat162 t = __floats2bfloat162_rn(lo, hi);
    return *(uint32_t*)&t;
}

#define LDSM4(d, addr) \
    asm volatile("ldmatrix.sync.aligned.m8n8.x4.shared.b16 {%0,%1,%2,%3}, [%4];" \
                 : "=r"((d)[0]), "=r"((d)[1]), "=r"((d)[2]), "=r"((d)[3]) : "r"(addr))
#define LDSM4T(d, addr) \
    asm volatile("ldmatrix.sync.aligned.m8n8.x4.trans.shared.b16 {%0,%1,%2,%3}, [%4];" \
                 : "=r"((d)[0]), "=r"((d)[1]), "=r"((d)[2]), "=r"((d)[3]) : "r"(addr))

#define MMA16816(c, a, b0, b1) \
    asm volatile("mma.sync.aligned.m16n8k16.row.col.f32.bf16.bf16.f32 " \
                 "{%0,%1,%2,%3}, {%4,%5,%6,%7}, {%8,%9}, {%0,%1,%2,%3};" \
                 : "+f"((c)[0]), "+f"((c)[1]), "+f"((c)[2]), "+f"((c)[3]) \
                 : "r"((a)[0]), "r"((a)[1]), "r"((a)[2]), "r"((a)[3]), \
                   "r"(b0), "r"(b1))

#define CP16(dst, src) \
    asm volatile("cp.async.cg.shared.global [%0], [%1], 16;" :: "r"(dst), "l"(src))

// ---------------- trig tables ------------------------------------------------
__global__ void trig_kernel() {
    int i = blockIdx.x*blockDim.x + threadIdx.x;
    if (i >= NS*(HD/2)) return;
    int pos = i >> 5;
    int j   = i & 31;
    double angle = exp(-((double)j/31.0)*log(10000.0));
    double arg = (double)pos * angle;
    g_sin[i] = (float)sin(arg);
    g_cos[i] = (float)cos(arg);
}

// ---------------- fp32 -> (bf16 hi, bf16 lo) split --------------------------
static __device__ __forceinline__ void split4(const float* __restrict__ src,
                                              __nv_bfloat16* __restrict__ d1,
                                              __nv_bfloat16* __restrict__ d2,
                                              size_t i) {
    float4 v = *(const float4*)(src + i);
    float a0=v.x, a1=v.y, a2=v.z, a3=v.w;
    __nv_bfloat16 h0=__float2bfloat16(a0), h1=__float2bfloat16(a1),
                  h2=__float2bfloat16(a2), h3=__float2bfloat16(a3);
    ushort4 u1, u2;
    u1.x=__bfloat16_as_ushort(h0); u1.y=__bfloat16_as_ushort(h1);
    u1.z=__bfloat16_as_ushort(h2); u1.w=__bfloat16_as_ushort(h3);
    u2.x=__bfloat16_as_ushort(__float2bfloat16(a0-__bfloat162float(h0)));
    u2.y=__bfloat16_as_ushort(__float2bfloat16(a1-__bfloat162float(h1)));
    u2.z=__bfloat16_as_ushort(__float2bfloat16(a2-__bfloat162float(h2)));
    u2.w=__bfloat16_as_ushort(__float2bfloat16(a3-__bfloat162float(h3)));
    *(ushort4*)(d1 + i) = u1;
    *(ushort4*)(d2 + i) = u2;
}

__global__ __launch_bounds__(256)
void split_kernel(const float* __restrict__ src,
                  __nv_bfloat16* __restrict__ d1,
                  __nv_bfloat16* __restrict__ d2, int n) {
    size_t i = ((size_t)blockIdx.x*blockDim.x + threadIdx.x) * 4;
    if (i >= (size_t)n) return;
    split4(src, d1, d2, i);
}

// three weights -> concatenated split buffers, one launch
__global__ __launch_bounds__(256)
void split3_kernel(const float* __restrict__ w0, const float* __restrict__ w1,
                   const float* __restrict__ w2) {
    int seg = blockIdx.y;
    size_t i = ((size_t)blockIdx.x*blockDim.x + threadIdx.x) * 4;
    if (i >= (size_t)ND*ND) return;
    const float* src = (seg==0) ? w0 : (seg==1) ? w1 : w2;
    split4(src, g_b1 + (size_t)seg*ND*ND, g_b2 + (size_t)seg*ND*ND, i);
}

// ---------------- HMMA bf16x3 GEMM: C = A @ B^T, 2-stage (R4 config) --------
// MODE 0: write fp32 C.  MODE 3: fused QKV (z selects weight slice + output,
//         z<2 applies RoPE before split).
#define GT_LDB   80            // bytes per smem row (40 bf16)
#define GT_TILE  (128*GT_LDB)  // 10240
#define GT_STAGE (4*GT_TILE)   // 40960
#define GEMM_DYNSMEM (2*GT_STAGE)

template<int MODE>
__global__ __launch_bounds__(256, 2)
void gemm_mma(const __nv_bfloat16* __restrict__ A1, const __nv_bfloat16* __restrict__ A2,
              const __nv_bfloat16* __restrict__ B1, const __nv_bfloat16* __restrict__ B2,
              float* __restrict__ C, int M, int N, int K)
{
    extern __shared__ char dsm[];
    uint32_t smb = smem_u32(dsm);
    int tid = threadIdx.x, lane = tid & 31, wid = tid >> 5;
    int wm = wid & 1, wn = wid >> 1;           // 2x4 warp grid
    int m0 = blockIdx.y * 128, n0 = blockIdx.x * 128;
    int z = (MODE == 3) ? blockIdx.z : 0;
    size_t wslice = (size_t)z * ND * ND;

    const __nv_bfloat16* pa1 = A1 + (size_t)m0 * K;
    const __nv_bfloat16* pa2 = A2 + (size_t)m0 * K;
    const __nv_bfloat16* pb1 = B1 + wslice + (size_t)n0 * K;
    const __nv_bfloat16* pb2 = B2 + wslice + (size_t)n0 * K;

    int v0r = tid >> 2,          v0c = tid & 3;
    int v1r = (tid + 256) >> 2,  v1c = tid & 3;

    int q = lane >> 3, r = lane & 7;
    uint32_t aoff = (uint32_t)((wm*64 + r + 8*(q & 1)) * GT_LDB + 16*(q >> 1));
    uint32_t boff = (uint32_t)((wn*32 + r + 8*(q >> 1)) * GT_LDB + 16*(q & 1));

    float acc[4][4][4] = {};

    int nk = K / 32;
#define LOAD_STAGE(s, k0)                                                        \
    {                                                                            \
        uint32_t st = smb + ((s) & 1) * GT_STAGE;                                \
        uint32_t o0 = (uint32_t)(v0r * GT_LDB + v0c * 16);                       \
        uint32_t o1 = (uint32_t)(v1r * GT_LDB + v1c * 16);                       \
        size_t g0 = (size_t)v0r * K + (k0) + v0c * 8;                            \
        size_t g1 = (size_t)v1r * K + (k0) + v1c * 8;                            \
        CP16(st + o0,             pa1 + g0);  CP16(st + o1,             pa1 + g1);\
        CP16(st + GT_TILE   + o0, pa2 + g0);  CP16(st + GT_TILE   + o1, pa2 + g1);\
        CP16(st + 2*GT_TILE + o0, pb1 + g0);  CP16(st + 2*GT_TILE + o1, pb1 + g1);\
        CP16(st + 3*GT_TILE + o0, pb2 + g0);  CP16(st + 3*GT_TILE + o1, pb2 + g1);\
        asm volatile("cp.async.commit_group;");                                  \
    }

    LOAD_STAGE(0, 0)
    asm volatile("cp.async.wait_group 0;");
    __syncthreads();

    for (int s = 0; s < nk; s++) {
        if (s + 1 < nk) LOAD_STAGE(s + 1, (s + 1) * 32)
        uint32_t st = smb + (s & 1) * GT_STAGE;
#pragma unroll
        for (int kk = 0; kk < 2; kk++) {
            uint32_t ka = st + aoff + kk*32;
            uint32_t kb = st + boff + kk*32;
            uint32_t a1f[4][4], a2f[4][4], bfr[2][4];
#pragma unroll
            for (int i = 0; i < 4; i++) LDSM4(a1f[i], ka + i*16*GT_LDB);
#pragma unroll
            for (int i = 0; i < 4; i++) LDSM4(a2f[i], ka + GT_TILE + i*16*GT_LDB);
#pragma unroll
            for (int j = 0; j < 2; j++) LDSM4(bfr[j], kb + 2*GT_TILE + j*16*GT_LDB);
#pragma unroll
            for (int i = 0; i < 4; i++)
#pragma unroll
                for (int jj = 0; jj < 4; jj++)
                    MMA16816(acc[i][jj], a1f[i], bfr[jj>>1][(jj&1)*2], bfr[jj>>1][(jj&1)*2+1]);
#pragma unroll
            for (int i = 0; i < 4; i++)
#pragma unroll
                for (int jj = 0; jj < 4; jj++)
                    MMA16816(acc[i][jj], a2f[i], bfr[jj>>1][(jj&1)*2], bfr[jj>>1][(jj&1)*2+1]);
#pragma unroll
            for (int j = 0; j < 2; j++) LDSM4(bfr[j], kb + 3*GT_TILE + j*16*GT_LDB);
#pragma unroll
            for (int i = 0; i < 4; i++)
#pragma unroll
                for (int jj = 0; jj < 4; jj++)
                    MMA16816(acc[i][jj], a1f[i], bfr[jj>>1][(jj&1)*2], bfr[jj>>1][(jj&1)*2+1]);
        }
        if (s + 1 < nk) asm volatile("cp.async.wait_group 0;");
        __syncthreads();
    }

    // epilogue
    int mrow = m0 + wm*64 + (lane >> 2);
    int ncol = n0 + wn*32 + (lane & 3)*2;
    __nv_bfloat16 *C1 = nullptr, *C2 = nullptr;
    if (MODE == 3) {
        C1 = (z==0) ? g_q1 : (z==1) ? g_k1 : g_v1;
        C2 = (z==0) ? g_q2 : (z==1) ? g_k2 : g_v2;
    }
#pragma unroll
    for (int i = 0; i < 4; i++) {
#pragma unroll
        for (int jj = 0; jj < 4; jj++) {
            if (MODE == 0) {
                *(float2*)(C + (size_t)(mrow + i*16)     * N + ncol + jj*8) =
                    make_float2(acc[i][jj][0], acc[i][jj][1]);
                *(float2*)(C + (size_t)(mrow + i*16 + 8) * N + ncol + jj*8) =
                    make_float2(acc[i][jj][2], acc[i][jj][3]);
            } else {
                int col = ncol + jj*8;
#pragma unroll
                for (int half = 0; half < 2; half++) {
                    int row = mrow + i*16 + half*8;
                    float c0 = acc[i][jj][half*2], c1 = acc[i][jj][half*2+1];
                    float y0 = c0, y1 = c1;
                    if (z < 2) {   // RoPE for q, k
                        int pos = row & (NS-1);
                        int j = (col & 63) >> 1;
                        float sn = g_sin[pos*32 + j], cs = g_cos[pos*32 + j];
                        y0 = c0*cs - c1*sn;
                        y1 = c1*cs + c0*sn;
                    }
                    __nv_bfloat16 h0 = __float2bfloat16(y0), h1 = __float2bfloat16(y1);
                    uint32_t u1 = (uint32_t)__bfloat16_as_ushort(h0) |
                                  ((uint32_t)__bfloat16_as_ushort(h1) << 16);
                    uint32_t u2 = packbf2(y0 - __bfloat162float(h0),
                                          y1 - __bfloat162float(h1));
                    *(uint32_t*)(C1 + (size_t)row * N + col) = u1;
                    *(uint32_t*)(C2 + (size_t)row * N + col) = u2;
                }
            }
        }
    }
}

// ---------------- attention: HMMA bf16x3, causal decay mask -----------------
// block: 128 q-rows of one (b,h); 8 warps x 16 rows. t-tiles of 64 rows,
// K/V double-buffered. S stays in registers. Epilogue fuses LN+SiLU+split.
#define AT_LDB    144                        // smem row stride (bytes)
#define AT_Q1     0
#define AT_Q2     (128*AT_LDB)               // 18432
#define AT_STAGE0 (2*128*AT_LDB)             // 36864
#define AT_KTILE  (64*AT_LDB)                // 9216
#define AT_STAGE_SZ (4*AT_KTILE)             // 36864
#define ATTN_SMEM (AT_STAGE0 + 2*AT_STAGE_SZ)  // 110592

__global__ __launch_bounds__(256)
void attn_mma_kernel(const float* __restrict__ lnw, const float* __restrict__ lnb) {
    extern __shared__ char smc[];
    uint32_t smb = smem_u32(smc);
    int tid = threadIdx.x, lane = tid & 31, wid = tid >> 5;
    int qb = (int)(gridDim.x - 1 - blockIdx.x);   // heavy blocks first
    int h = blockIdx.y, bb = blockIdx.z;
    int q0 = qb * 128;
    size_t rowbase = (size_t)bb * NS;
    size_t headoff = (size_t)h * HD;
    float dec = (float)log(1.0 - exp2(-5.0 - (double)h));   // negative

    // ---- load Q tile (both splits) ----
#pragma unroll
    for (int it = 0; it < 8; it++) {
        int idx = tid + it*256;               // 0..2047
        int t  = idx >> 10;                   // 0:q1 1:q2
        int rr = (idx >> 3) & 127;
        int cc = idx & 7;
        const __nv_bfloat16* src = (t ? g_q2 : g_q1) +
            (rowbase + q0 + rr)*ND + headoff + cc*8;
        uint32_t dst = smb + (t ? AT_Q2 : AT_Q1) + rr*AT_LDB + cc*16;
        CP16(dst, src);
    }

#define AT_LOAD(stage, t0_)                                                    \
    {                                                                          \
        uint32_t stb = smb + AT_STAGE0 + (stage)*AT_STAGE_SZ;                  \
        _Pragma("unroll")                                                      \
        for (int it = 0; it < 8; it++) {                                       \
            int idx = tid + it*256;                                            \
            int ts = idx >> 9;                                                 \
            int rr = (idx >> 3) & 63;                                          \
            int cc = idx & 7;                                                  \
            const __nv_bfloat16* sp =                                          \
                (ts==0 ? g_k1 : ts==1 ? g_k2 : ts==2 ? g_v1 : g_v2) +          \
                (rowbase + (t0_) + rr)*ND + headoff + cc*8;                    \
            CP16(stb + ts*AT_KTILE + rr*AT_LDB + cc*16, sp);                   \
        }                                                                      \
        asm volatile("cp.async.commit_group;");                                \
    }

    AT_LOAD(0, 0)
    asm volatile("cp.async.wait_group 0;");
    __syncthreads();

    int wr = wid * 16;
    int qlo = lane >> 2;                      // 0..7 row within 8
    uint32_t aoff = (uint32_t)((wr + (lane & 7) + 8*((lane >> 3) & 1))*AT_LDB
                               + 16*(lane >> 4));
    uint32_t boff = (uint32_t)(((lane & 7) + 8*((lane >> 3) >> 1))*AT_LDB
                               + 16*((lane >> 3) & 1));
    uint32_t voff = (uint32_t)((lane & 15)*AT_LDB + 16*(lane >> 4));

    float oacc[8][4] = {};
    float mul8 = __expf(dec * 8.0f);
    int ntt = 2*qb + 2;

    for (int tt = 0; tt < ntt; tt++) {
        int t0 = tt * 64;
        if (tt + 1 < ntt) AT_LOAD((tt+1) & 1, (tt+1)*64)

        uint32_t stb = smb + AT_STAGE0 + (tt & 1)*AT_STAGE_SZ;
        bool active = (q0 + wr + 15) >= t0;
        if (active) {
            // ---- S = Q K^T (bf16x3) ----
            float s[8][4] = {};
#pragma unroll
            for (int kk = 0; kk < 4; kk++) {
                uint32_t a1f[4], a2f[4];
                LDSM4(a1f, smb + AT_Q1 + aoff + kk*32);
                LDSM4(a2f, smb + AT_Q2 + aoff + kk*32);
#pragma unroll
                for (int nc = 0; nc < 4; nc++) {
                    uint32_t f1[4], f2[4];
                    LDSM4(f1, stb + boff + nc*16*AT_LDB + kk*32);
                    LDSM4(f2, stb + AT_KTILE + boff + nc*16*AT_LDB + kk*32);
                    MMA16816(s[2*nc],   a1f, f1[0], f1[1]);
                    MMA16816(s[2*nc+1], a1f, f1[2], f1[3]);
                    MMA16816(s[2*nc],   a2f, f1[0], f1[1]);
                    MMA16816(s[2*nc+1], a2f, f1[2], f1[3]);
                    MMA16816(s[2*nc],   a1f, f2[0], f2[1]);
                    MMA16816(s[2*nc+1], a1f, f2[2], f2[3]);
                }
            }
            // ---- decay mask (factored) + causal ----
            float rowf0 = __expf(dec * (float)(q0 + wr + qlo - t0));
            float rowf1 = rowf0 * mul8;
            float colf[8][2];
#pragma unroll
            for (int nt = 0; nt < 8; nt++)
#pragma unroll
                for (int par = 0; par < 2; par++)
                    colf[nt][par] = __expf(-dec * (float)(nt*8 + (lane&3)*2 + par));
            bool needcmp = (q0 + wr) < (t0 + 63);
#pragma unroll
            for (int nt = 0; nt < 8; nt++)
#pragma unroll
                for (int e = 0; e < 4; e++) {
                    int rloc = qlo + ((e >= 2) ? 8 : 0);
                    int cloc = nt*8 + (lane&3)*2 + (e & 1);
                    float m = ((e >= 2) ? rowf1 : rowf0) * colf[nt][e & 1];
                    if (needcmp && (q0 + wr + rloc) < (t0 + cloc)) m = 0.f;
                    s[nt][e] *= m;
                }
            // ---- split S in-register, O += S V (bf16x3) ----
#pragma unroll
            for (int kt = 0; kt < 4; kt++) {
                uint32_t sp1[4], sp2[4];
#pragma unroll
                for (int j = 0; j < 4; j++) {
                    int nt = 2*kt + (j >> 1);
                    int e0 = (j & 1) * 2;
                    float x0 = s[nt][e0], x1 = s[nt][e0+1];
                    __nv_bfloat16 h0 = __float2bfloat16(x0), h1 = __float2bfloat16(x1);
                    sp1[j] = (uint32_t)__bfloat16_as_ushort(h0) |
                             ((uint32_t)__bfloat16_as_ushort(h1) << 16);
                    sp2[j] = packbf2(x0 - __bfloat162float(h0),
                                     x1 - __bfloat162float(h1));
                }
#pragma unroll
                for (int nv = 0; nv < 4; nv++) {
                    uint32_t f1[4], f2[4];
                    LDSM4T(f1, stb + 2*AT_KTILE + voff + kt*16*AT_LDB + nv*32);
                    LDSM4T(f2, stb + 3*AT_KTILE + voff + kt*16*AT_LDB + nv*32);
                    MMA16816(oacc[2*nv],   sp1, f1[0], f1[1]);
                    MMA16816(oacc[2*nv+1], sp1, f1[2], f1[3]);
                    MMA16816(oacc[2*nv],   sp2, f1[0], f1[1]);
                    MMA16816(oacc[2*nv+1], sp2, f1[2], f1[3]);
                    MMA16816(oacc[2*nv],   sp1, f2[0], f2[1]);
                    MMA16816(oacc[2*nv+1], sp1, f2[2], f2[3]);
                }
            }
        }
        if (tt + 1 < ntt) asm volatile("cp.async.wait_group 0;");
        __syncthreads();
    }

    // ---- fused LayerNorm(64) + SiLU + bf16 split, write to g_a1/g_a2 ----
    int colbase = (lane & 3)*2;
#pragma unroll
    for (int half = 0; half < 2; half++) {
        float sum = 0.f, sq = 0.f;
#pragma unroll
        for (int nt = 0; nt < 8; nt++) {
            float v0 = oacc[nt][half*2], v1 = oacc[nt][half*2+1];
            sum += v0 + v1;
            sq  += v0*v0 + v1*v1;
        }
        sum += __shfl_xor_sync(0xffffffffu, sum, 1);
        sq  += __shfl_xor_sync(0xffffffffu, sq, 1);
        sum += __shfl_xor_sync(0xffffffffu, sum, 2);
        sq  += __shfl_xor_sync(0xffffffffu, sq, 2);
        float mean = sum * (1.f/64.f);
        float var  = sq * (1.f/64.f) - mean*mean;
        float rs = rsqrtf(var + 1e-5f);
        size_t rbase = (rowbase + q0 + wr + qlo + half*8)*ND + headoff;
#pragma unroll
        for (int nt = 0; nt < 8; nt++) {
            int c = nt*8 + colbase;
            float y0 = (oacc[nt][half*2]   - mean)*rs*lnw[c]   + lnb[c];
            float y1 = (oacc[nt][half*2+1] - mean)*rs*lnw[c+1] + lnb[c+1];
            y0 = y0 / (1.f + __expf(-y0));
            y1 = y1 / (1.f + __expf(-y1));
            __nv_bfloat16 h0 = __float2bfloat16(y0), h1 = __float2bfloat16(y1);
            uint32_t u1 = (uint32_t)__bfloat16_as_ushort(h0) |
                          ((uint32_t)__bfloat16_as_ushort(h1) << 16);
            uint32_t u2 = packbf2(y0 - __bfloat162float(h0),
                                  y1 - __bfloat162float(h1));
            *(uint32_t*)(g_a1 + rbase + c) = u1;
            *(uint32_t*)(g_a2 + rbase + c) = u2;
        }
    }
}

// ---------------- launcher ---------------------------------------------------
extern "C" void kernel_launch(void* const* d_in, const int* in_sizes, int n_in,
                              void* d_out, int out_size) {
    const float* x   = (const float*)d_in[0];
    const float* Wq  = (const float*)d_in[1];
    const float* Wk  = (const float*)d_in[2];
    const float* Wv  = (const float*)d_in[3];
    const float* Wo  = (const float*)d_in[4];
    const float* lnw = (const float*)d_in[5];
    const float* lnb = (const float*)d_in[6];
    float* out = (float*)d_out;

    __nv_bfloat16 *a1, *a2, *b1, *b2;
    cudaGetSymbolAddress((void**)&a1, g_a1);
    cudaGetSymbolAddress((void**)&a2, g_a2);
    cudaGetSymbolAddress((void**)&b1, g_b1);
    cudaGetSymbolAddress((void**)&b2, g_b2);

    trig_kernel<<<(NS*(HD/2)+255)/256, 256>>>();

    cudaFuncSetAttribute(gemm_mma<0>, cudaFuncAttributeMaxDynamicSharedMemorySize, GEMM_DYNSMEM);
    cudaFuncSetAttribute(gemm_mma<3>, cudaFuncAttributeMaxDynamicSharedMemorySize, GEMM_DYNSMEM);
    cudaFuncSetAttribute(attn_mma_kernel, cudaFuncAttributeMaxDynamicSharedMemorySize, ATTN_SMEM);

    dim3 wsplit((ND*ND/4 + 255)/256);
    dim3 asplit(((size_t)NM*ND/4 + 255)/256);

    // split activations (x) and all three weights
    split_kernel<<<asplit, 256>>>(x, a1, a2, NM*ND);
    split3_kernel<<<dim3(ND*ND/4/256, 3), 256>>>(Wq, Wk, Wv);

    // fused QKV projection: one launch, grid.z selects weight + output (+RoPE)
    gemm_mma<3><<<dim3(ND/128, NM/128, 3), 256, GEMM_DYNSMEM>>>(
        a1, a2, b1, b2, nullptr, NM, ND, ND);

    // attention writes LN(SiLU(O)) bf16 splits directly into g_a1/g_a2
    attn_mma_kernel<<<dim3(NS/128, NH, NB), 256, ATTN_SMEM>>>(lnw, lnb);

    split_kernel<<<wsplit, 256>>>(Wo, b1, b2, ND*ND);
    gemm_mma<0><<<dim3(ND/128, NM/128), 256, GEMM_DYNSMEM>>>(
        a1, a2, b1, b2, out, NM, ND, ND);
}

// round 10
// speedup vs baseline: 1.0001x; 1.0001x over previous
#include <cuda_runtime.h>
#include <cuda_bf16.h>
#include <math.h>
#include <stdint.h>

// Problem constants
#define NB 4
#define NS 2048
#define ND 1024
#define NH 16
#define HD 64
#define NM (NB*NS)          // 8192 rows

// ---------------- scratch (device globals: no allocation allowed) ----------
__device__ float g_sin[NS*(HD/2)];
__device__ float g_cos[NS*(HD/2)];
// bf16 split buffers
__device__ __nv_bfloat16 g_q1[(size_t)NM*ND];
__device__ __nv_bfloat16 g_q2[(size_t)NM*ND];
__device__ __nv_bfloat16 g_k1[(size_t)NM*ND];
__device__ __nv_bfloat16 g_k2[(size_t)NM*ND];
__device__ __nv_bfloat16 g_v1[(size_t)NM*ND];
__device__ __nv_bfloat16 g_v2[(size_t)NM*ND];
__device__ __nv_bfloat16 g_a1[(size_t)NM*ND];
__device__ __nv_bfloat16 g_a2[(size_t)NM*ND];
__device__ __nv_bfloat16 g_b1[(size_t)3*ND*ND];
__device__ __nv_bfloat16 g_b2[(size_t)3*ND*ND];

// ---------------- helpers ----------------------------------------------------
static __device__ __forceinline__ uint32_t smem_u32(const void* p) {
    uint32_t a;
    asm("{ .reg .u64 t; cvta.to.shared.u64 t, %1; cvt.u32.u64 %0, t; }"
        : "=r"(a) : "l"(p));
    return a;
}
static __device__ __forceinline__ uint32_t packbf2(float lo, float hi) {
    __nv_bfloat162 t = __floats2bfloat162_rn(lo, hi);
    return *(uint32_t*)&t;
}

#define LDSM4(d, addr) \
    asm volatile("ldmatrix.sync.aligned.m8n8.x4.shared.b16 {%0,%1,%2,%3}, [%4];" \
                 : "=r"((d)[0]), "=r"((d)[1]), "=r"((d)[2]), "=r"((d)[3]) : "r"(addr))
#define LDSM4T(d, addr) \
    asm volatile("ldmatrix.sync.aligned.m8n8.x4.trans.shared.b16 {%0,%1,%2,%3}, [%4];" \
                 : "=r"((d)[0]), "=r"((d)[1]), "=r"((d)[2]), "=r"((d)[3]) : "r"(addr))

#define MMA16816(c, a, b0, b1) \
    asm volatile("mma.sync.aligned.m16n8k16.row.col.f32.bf16.bf16.f32 " \
                 "{%0,%1,%2,%3}, {%4,%5,%6,%7}, {%8,%9}, {%0,%1,%2,%3};" \
                 : "+f"((c)[0]), "+f"((c)[1]), "+f"((c)[2]), "+f"((c)[3]) \
                 : "r"((a)[0]), "r"((a)[1]), "r"((a)[2]), "r"((a)[3]), \
                   "r"(b0), "r"(b1))

#define CP16(dst, src) \
    asm volatile("cp.async.cg.shared.global [%0], [%1], 16;" :: "r"(dst), "l"(src))

// ---------------- trig tables ------------------------------------------------
__global__ void trig_kernel() {
    int i = blockIdx.x*blockDim.x + threadIdx.x;
    if (i >= NS*(HD/2)) return;
    int pos = i >> 5;
    int j   = i & 31;
    double angle = exp(-((double)j/31.0)*log(10000.0));
    double arg = (double)pos * angle;
    g_sin[i] = (float)sin(arg);
    g_cos[i] = (float)cos(arg);
}

// ---------------- fp32 -> (bf16 hi, bf16 lo) split --------------------------
static __device__ __forceinline__ void split4(const float* __restrict__ src,
                                              __nv_bfloat16* __restrict__ d1,
                                              __nv_bfloat16* __restrict__ d2,
                                              size_t i) {
    float4 v = *(const float4*)(src + i);
    float a0=v.x, a1=v.y, a2=v.z, a3=v.w;
    __nv_bfloat16 h0=__float2bfloat16(a0), h1=__float2bfloat16(a1),
                  h2=__float2bfloat16(a2), h3=__float2bfloat16(a3);
    ushort4 u1, u2;
    u1.x=__bfloat16_as_ushort(h0); u1.y=__bfloat16_as_ushort(h1);
    u1.z=__bfloat16_as_ushort(h2); u1.w=__bfloat16_as_ushort(h3);
    u2.x=__bfloat16_as_ushort(__float2bfloat16(a0-__bfloat162float(h0)));
    u2.y=__bfloat16_as_ushort(__float2bfloat16(a1-__bfloat162float(h1)));
    u2.z=__bfloat16_as_ushort(__float2bfloat16(a2-__bfloat162float(h2)));
    u2.w=__bfloat16_as_ushort(__float2bfloat16(a3-__bfloat162float(h3)));
    *(ushort4*)(d1 + i) = u1;
    *(ushort4*)(d2 + i) = u2;
}

__global__ __launch_bounds__(256)
void split_kernel(const float* __restrict__ src,
                  __nv_bfloat16* __restrict__ d1,
                  __nv_bfloat16* __restrict__ d2, int n) {
    size_t i = ((size_t)blockIdx.x*blockDim.x + threadIdx.x) * 4;
    if (i >= (size_t)n) return;
    split4(src, d1, d2, i);
}

// three weights -> concatenated split buffers, one launch
__global__ __launch_bounds__(256)
void split3_kernel(const float* __restrict__ w0, const float* __restrict__ w1,
                   const float* __restrict__ w2) {
    int seg = blockIdx.y;
    size_t i = ((size_t)blockIdx.x*blockDim.x + threadIdx.x) * 4;
    if (i >= (size_t)ND*ND) return;
    const float* src = (seg==0) ? w0 : (seg==1) ? w1 : w2;
    split4(src, g_b1 + (size_t)seg*ND*ND, g_b2 + (size_t)seg*ND*ND, i);
}

// ---------------- HMMA bf16x3 GEMM: C = A @ B^T, 2-stage (R4 config) --------
// MODE 0: write fp32 C.  MODE 3: fused QKV (z selects weight slice + output,
//         z<2 applies RoPE before split).
#define GT_LDB   80            // bytes per smem row (40 bf16)
#define GT_TILE  (128*GT_LDB)  // 10240
#define GT_STAGE (4*GT_TILE)   // 40960
#define GEMM_DYNSMEM (2*GT_STAGE)

template<int MODE>
__global__ __launch_bounds__(256, 2)
void gemm_mma(const __nv_bfloat16* __restrict__ A1, const __nv_bfloat16* __restrict__ A2,
              const __nv_bfloat16* __restrict__ B1, const __nv_bfloat16* __restrict__ B2,
              float* __restrict__ C, int M, int N, int K)
{
    extern __shared__ char dsm[];
    uint32_t smb = smem_u32(dsm);
    int tid = threadIdx.x, lane = tid & 31, wid = tid >> 5;
    int wm = wid & 1, wn = wid >> 1;           // 2x4 warp grid
    int m0 = blockIdx.y * 128, n0 = blockIdx.x * 128;
    int z = (MODE == 3) ? blockIdx.z : 0;
    size_t wslice = (size_t)z * ND * ND;

    const __nv_bfloat16* pa1 = A1 + (size_t)m0 * K;
    const __nv_bfloat16* pa2 = A2 + (size_t)m0 * K;
    const __nv_bfloat16* pb1 = B1 + wslice + (size_t)n0 * K;
    const __nv_bfloat16* pb2 = B2 + wslice + (size_t)n0 * K;

    int v0r = tid >> 2,          v0c = tid & 3;
    int v1r = (tid + 256) >> 2,  v1c = tid & 3;

    int q = lane >> 3, r = lane & 7;
    uint32_t aoff = (uint32_t)((wm*64 + r + 8*(q & 1)) * GT_LDB + 16*(q >> 1));
    uint32_t boff = (uint32_t)((wn*32 + r + 8*(q >> 1)) * GT_LDB + 16*(q & 1));

    float acc[4][4][4] = {};

    int nk = K / 32;
#define LOAD_STAGE(s, k0)                                                        \
    {                                                                            \
        uint32_t st = smb + ((s) & 1) * GT_STAGE;                                \
        uint32_t o0 = (uint32_t)(v0r * GT_LDB + v0c * 16);                       \
        uint32_t o1 = (uint32_t)(v1r * GT_LDB + v1c * 16);                       \
        size_t g0 = (size_t)v0r * K + (k0) + v0c * 8;                            \
        size_t g1 = (size_t)v1r * K + (k0) + v1c * 8;                            \
        CP16(st + o0,             pa1 + g0);  CP16(st + o1,             pa1 + g1);\
        CP16(st + GT_TILE   + o0, pa2 + g0);  CP16(st + GT_TILE   + o1, pa2 + g1);\
        CP16(st + 2*GT_TILE + o0, pb1 + g0);  CP16(st + 2*GT_TILE + o1, pb1 + g1);\
        CP16(st + 3*GT_TILE + o0, pb2 + g0);  CP16(st + 3*GT_TILE + o1, pb2 + g1);\
        asm volatile("cp.async.commit_group;");                                  \
    }

    LOAD_STAGE(0, 0)
    asm volatile("cp.async.wait_group 0;");
    __syncthreads();

    for (int s = 0; s < nk; s++) {
        if (s + 1 < nk) LOAD_STAGE(s + 1, (s + 1) * 32)
        uint32_t st = smb + (s & 1) * GT_STAGE;
#pragma unroll
        for (int kk = 0; kk < 2; kk++) {
            uint32_t ka = st + aoff + kk*32;
            uint32_t kb = st + boff + kk*32;
            uint32_t a1f[4][4], a2f[4][4], bfr[2][4];
#pragma unroll
            for (int i = 0; i < 4; i++) LDSM4(a1f[i], ka + i*16*GT_LDB);
#pragma unroll
            for (int i = 0; i < 4; i++) LDSM4(a2f[i], ka + GT_TILE + i*16*GT_LDB);
#pragma unroll
            for (int j = 0; j < 2; j++) LDSM4(bfr[j], kb + 2*GT_TILE + j*16*GT_LDB);
#pragma unroll
            for (int i = 0; i < 4; i++)
#pragma unroll
                for (int jj = 0; jj < 4; jj++)
                    MMA16816(acc[i][jj], a1f[i], bfr[jj>>1][(jj&1)*2], bfr[jj>>1][(jj&1)*2+1]);
#pragma unroll
            for (int i = 0; i < 4; i++)
#pragma unroll
                for (int jj = 0; jj < 4; jj++)
                    MMA16816(acc[i][jj], a2f[i], bfr[jj>>1][(jj&1)*2], bfr[jj>>1][(jj&1)*2+1]);
#pragma unroll
            for (int j = 0; j < 2; j++) LDSM4(bfr[j], kb + 3*GT_TILE + j*16*GT_LDB);
#pragma unroll
            for (int i = 0; i < 4; i++)
#pragma unroll
                for (int jj = 0; jj < 4; jj++)
                    MMA16816(acc[i][jj], a1f[i], bfr[jj>>1][(jj&1)*2], bfr[jj>>1][(jj&1)*2+1]);
        }
        if (s + 1 < nk) asm volatile("cp.async.wait_group 0;");
        __syncthreads();
    }

    // epilogue
    int mrow = m0 + wm*64 + (lane >> 2);
    int ncol = n0 + wn*32 + (lane & 3)*2;
    __nv_bfloat16 *C1 = nullptr, *C2 = nullptr;
    if (MODE == 3) {
        C1 = (z==0) ? g_q1 : (z==1) ? g_k1 : g_v1;
        C2 = (z==0) ? g_q2 : (z==1) ? g_k2 : g_v2;
    }
#pragma unroll
    for (int i = 0; i < 4; i++) {
#pragma unroll
        for (int jj = 0; jj < 4; jj++) {
            if (MODE == 0) {
                *(float2*)(C + (size_t)(mrow + i*16)     * N + ncol + jj*8) =
                    make_float2(acc[i][jj][0], acc[i][jj][1]);
                *(float2*)(C + (size_t)(mrow + i*16 + 8) * N + ncol + jj*8) =
                    make_float2(acc[i][jj][2], acc[i][jj][3]);
            } else {
                int col = ncol + jj*8;
#pragma unroll
                for (int half = 0; half < 2; half++) {
                    int row = mrow + i*16 + half*8;
                    float c0 = acc[i][jj][half*2], c1 = acc[i][jj][half*2+1];
                    float y0 = c0, y1 = c1;
                    if (z < 2) {   // RoPE for q, k
                        int pos = row & (NS-1);
                        int j = (col & 63) >> 1;
                        float sn = g_sin[pos*32 + j], cs = g_cos[pos*32 + j];
                        y0 = c0*cs - c1*sn;
                        y1 = c1*cs + c0*sn;
                    }
                    __nv_bfloat16 h0 = __float2bfloat16(y0), h1 = __float2bfloat16(y1);
                    uint32_t u1 = (uint32_t)__bfloat16_as_ushort(h0) |
                                  ((uint32_t)__bfloat16_as_ushort(h1) << 16);
                    uint32_t u2 = packbf2(y0 - __bfloat162float(h0),
                                          y1 - __bfloat162float(h1));
                    *(uint32_t*)(C1 + (size_t)row * N + col) = u1;
                    *(uint32_t*)(C2 + (size_t)row * N + col) = u2;
                }
            }
        }
    }
}

// ---------------- attention: HMMA bf16x3, causal decay mask -----------------
// block: 128 q-rows of one (b,h); 8 warps x 16 rows. t-tiles of 64 rows,
// K/V double-buffered. S stays in registers. Epilogue fuses LN+SiLU+split.
#define AT_LDB    144                        // smem row stride (bytes)
#define AT_Q1     0
#define AT_Q2     (128*AT_LDB)               // 18432
#define AT_STAGE0 (2*128*AT_LDB)             // 36864
#define AT_KTILE  (64*AT_LDB)                // 9216
#define AT_STAGE_SZ (4*AT_KTILE)             // 36864
#define ATTN_SMEM (AT_STAGE0 + 2*AT_STAGE_SZ)  // 110592

__global__ __launch_bounds__(256)
void attn_mma_kernel(const float* __restrict__ lnw, const float* __restrict__ lnb) {
    extern __shared__ char smc[];
    uint32_t smb = smem_u32(smc);
    int tid = threadIdx.x, lane = tid & 31, wid = tid >> 5;
    int qb = (int)(gridDim.x - 1 - blockIdx.x);   // heavy blocks first
    int h = blockIdx.y, bb = blockIdx.z;
    int q0 = qb * 128;
    size_t rowbase = (size_t)bb * NS;
    size_t headoff = (size_t)h * HD;
    float dec = (float)log(1.0 - exp2(-5.0 - (double)h));   // negative

    // ---- load Q tile (both splits) ----
#pragma unroll
    for (int it = 0; it < 8; it++) {
        int idx = tid + it*256;               // 0..2047
        int t  = idx >> 10;                   // 0:q1 1:q2
        int rr = (idx >> 3) & 127;
        int cc = idx & 7;
        const __nv_bfloat16* src = (t ? g_q2 : g_q1) +
            (rowbase + q0 + rr)*ND + headoff + cc*8;
        uint32_t dst = smb + (t ? AT_Q2 : AT_Q1) + rr*AT_LDB + cc*16;
        CP16(dst, src);
    }

#define AT_LOAD(stage, t0_)                                                    \
    {                                                                          \
        uint32_t stb = smb + AT_STAGE0 + (stage)*AT_STAGE_SZ;                  \
        _Pragma("unroll")                                                      \
        for (int it = 0; it < 8; it++) {                                       \
            int idx = tid + it*256;                                            \
            int ts = idx >> 9;                                                 \
            int rr = (idx >> 3) & 63;                                          \
            int cc = idx & 7;                                                  \
            const __nv_bfloat16* sp =                                          \
                (ts==0 ? g_k1 : ts==1 ? g_k2 : ts==2 ? g_v1 : g_v2) +          \
                (rowbase + (t0_) + rr)*ND + headoff + cc*8;                    \
            CP16(stb + ts*AT_KTILE + rr*AT_LDB + cc*16, sp);                   \
        }                                                                      \
        asm volatile("cp.async.commit_group;");                                \
    }

    AT_LOAD(0, 0)
    asm volatile("cp.async.wait_group 0;");
    __syncthreads();

    int wr = wid * 16;
    int qlo = lane >> 2;                      // 0..7 row within 8
    uint32_t aoff = (uint32_t)((wr + (lane & 7) + 8*((lane >> 3) & 1))*AT_LDB
                               + 16*(lane >> 4));
    uint32_t boff = (uint32_t)(((lane & 7) + 8*((lane >> 3) >> 1))*AT_LDB
                               + 16*((lane >> 3) & 1));
    uint32_t voff = (uint32_t)((lane & 15)*AT_LDB + 16*(lane >> 4));

    float oacc[8][4] = {};
    float mul8 = __expf(dec * 8.0f);
    int ntt = 2*qb + 2;

    for (int tt = 0; tt < ntt; tt++) {
        int t0 = tt * 64;
        if (tt + 1 < ntt) AT_LOAD((tt+1) & 1, (tt+1)*64)

        uint32_t stb = smb + AT_STAGE0 + (tt & 1)*AT_STAGE_SZ;
        bool active = (q0 + wr + 15) >= t0;
        if (active) {
            // ---- S = Q K^T (bf16x3) ----
            float s[8][4] = {};
#pragma unroll
            for (int kk = 0; kk < 4; kk++) {
                uint32_t a1f[4], a2f[4];
                LDSM4(a1f, smb + AT_Q1 + aoff + kk*32);
                LDSM4(a2f, smb + AT_Q2 + aoff + kk*32);
#pragma unroll
                for (int nc = 0; nc < 4; nc++) {
                    uint32_t f1[4], f2[4];
                    LDSM4(f1, stb + boff + nc*16*AT_LDB + kk*32);
                    LDSM4(f2, stb + AT_KTILE + boff + nc*16*AT_LDB + kk*32);
                    MMA16816(s[2*nc],   a1f, f1[0], f1[1]);
                    MMA16816(s[2*nc+1], a1f, f1[2], f1[3]);
                    MMA16816(s[2*nc],   a2f, f1[0], f1[1]);
                    MMA16816(s[2*nc+1], a2f, f1[2], f1[3]);
                    MMA16816(s[2*nc],   a1f, f2[0], f2[1]);
                    MMA16816(s[2*nc+1], a1f, f2[2], f2[3]);
                }
            }
            // ---- decay mask (factored) + causal ----
            float rowf0 = __expf(dec * (float)(q0 + wr + qlo - t0));
            float rowf1 = rowf0 * mul8;
            float colf[8][2];
#pragma unroll
            for (int nt = 0; nt < 8; nt++)
#pragma unroll
                for (int par = 0; par < 2; par++)
                    colf[nt][par] = __expf(-dec * (float)(nt*8 + (lane&3)*2 + par));
            bool needcmp = (q0 + wr) < (t0 + 63);
#pragma unroll
            for (int nt = 0; nt < 8; nt++)
#pragma unroll
                for (int e = 0; e < 4; e++) {
                    int rloc = qlo + ((e >= 2) ? 8 : 0);
                    int cloc = nt*8 + (lane&3)*2 + (e & 1);
                    float m = ((e >= 2) ? rowf1 : rowf0) * colf[nt][e & 1];
                    if (needcmp && (q0 + wr + rloc) < (t0 + cloc)) m = 0.f;
                    s[nt][e] *= m;
                }
            // ---- split S in-register, O += S V (bf16x3) ----
#pragma unroll
            for (int kt = 0; kt < 4; kt++) {
                uint32_t sp1[4], sp2[4];
#pragma unroll
                for (int j = 0; j < 4; j++) {
                    int nt = 2*kt + (j >> 1);
                    int e0 = (j & 1) * 2;
                    float x0 = s[nt][e0], x1 = s[nt][e0+1];
                    __nv_bfloat16 h0 = __float2bfloat16(x0), h1 = __float2bfloat16(x1);
                    sp1[j] = (uint32_t)__bfloat16_as_ushort(h0) |
                             ((uint32_t)__bfloat16_as_ushort(h1) << 16);
                    sp2[j] = packbf2(x0 - __bfloat162float(h0),
                                     x1 - __bfloat162float(h1));
                }
#pragma unroll
                for (int nv = 0; nv < 4; nv++) {
                    uint32_t f1[4], f2[4];
                    LDSM4T(f1, stb + 2*AT_KTILE + voff + kt*16*AT_LDB + nv*32);
                    LDSM4T(f2, stb + 3*AT_KTILE + voff + kt*16*AT_LDB + nv*32);
                    MMA16816(oacc[2*nv],   sp1, f1[0], f1[1]);
                    MMA16816(oacc[2*nv+1], sp1, f1[2], f1[3]);
                    MMA16816(oacc[2*nv],   sp2, f1[0], f1[1]);
                    MMA16816(oacc[2*nv+1], sp2, f1[2], f1[3]);
                    MMA16816(oacc[2*nv],   sp1, f2[0], f2[1]);
                    MMA16816(oacc[2*nv+1], sp1, f2[2], f2[3]);
                }
            }
        }
        if (tt + 1 < ntt) asm volatile("cp.async.wait_group 0;");
        __syncthreads();
    }

    // ---- fused LayerNorm(64) + SiLU + bf16 split, write to g_a1/g_a2 ----
    int colbase = (lane & 3)*2;
#pragma unroll
    for (int half = 0; half < 2; half++) {
        float sum = 0.f, sq = 0.f;
#pragma unroll
        for (int nt = 0; nt < 8; nt++) {
            float v0 = oacc[nt][half*2], v1 = oacc[nt][half*2+1];
            sum += v0 + v1;
            sq  += v0*v0 + v1*v1;
        }
        sum += __shfl_xor_sync(0xffffffffu, sum, 1);
        sq  += __shfl_xor_sync(0xffffffffu, sq, 1);
        sum += __shfl_xor_sync(0xffffffffu, sum, 2);
        sq  += __shfl_xor_sync(0xffffffffu, sq, 2);
        float mean = sum * (1.f/64.f);
        float var  = sq * (1.f/64.f) - mean*mean;
        float rs = rsqrtf(var + 1e-5f);
        size_t rbase = (rowbase + q0 + wr + qlo + half*8)*ND + headoff;
#pragma unroll
        for (int nt = 0; nt < 8; nt++) {
            int c = nt*8 + colbase;
            float y0 = (oacc[nt][half*2]   - mean)*rs*lnw[c]   + lnb[c];
            float y1 = (oacc[nt][half*2+1] - mean)*rs*lnw[c+1] + lnb[c+1];
            y0 = y0 / (1.f + __expf(-y0));
            y1 = y1 / (1.f + __expf(-y1));
            __nv_bfloat16 h0 = __float2bfloat16(y0), h1 = __float2bfloat16(y1);
            uint32_t u1 = (uint32_t)__bfloat16_as_ushort(h0) |
                          ((uint32_t)__bfloat16_as_ushort(h1) << 16);
            uint32_t u2 = packbf2(y0 - __bfloat162float(h0),
                                  y1 - __bfloat162float(h1));
            *(uint32_t*)(g_a1 + rbase + c) = u1;
            *(uint32_t*)(g_a2 + rbase + c) = u2;
        }
    }
}

// ---------------- launcher ---------------------------------------------------
extern "C" void kernel_launch(void* const* d_in, const int* in_sizes, int n_in,
                              void* d_out, int out_size) {
    const float* x   = (const float*)d_in[0];
    const float* Wq  = (const float*)d_in[1];
    const float* Wk  = (const float*)d_in[2];
    const float* Wv  = (const float*)d_in[3];
    const float* Wo  = (const float*)d_in[4];
    const float* lnw = (const float*)d_in[5];
    const float* lnb = (const float*)d_in[6];
    float* out = (float*)d_out;

    __nv_bfloat16 *a1, *a2, *b1, *b2;
    cudaGetSymbolAddress((void**)&a1, g_a1);
    cudaGetSymbolAddress((void**)&a2, g_a2);
    cudaGetSymbolAddress((void**)&b1, g_b1);
    cudaGetSymbolAddress((void**)&b2, g_b2);

    trig_kernel<<<(NS*(HD/2)+255)/256, 256>>>();

    cudaFuncSetAttribute(gemm_mma<0>, cudaFuncAttributeMaxDynamicSharedMemorySize, GEMM_DYNSMEM);
    cudaFuncSetAttribute(gemm_mma<3>, cudaFuncAttributeMaxDynamicSharedMemorySize, GEMM_DYNSMEM);
    cudaFuncSetAttribute(attn_mma_kernel, cudaFuncAttributeMaxDynamicSharedMemorySize, ATTN_SMEM);

    dim3 wsplit((ND*ND/4 + 255)/256);
    dim3 asplit(((size_t)NM*ND/4 + 255)/256);

    // split activations (x) and all three weights
    split_kernel<<<asplit, 256>>>(x, a1, a2, NM*ND);
    split3_kernel<<<dim3(ND*ND/4/256, 3), 256>>>(Wq, Wk, Wv);

    // fused QKV projection: one launch, grid.z selects weight + output (+RoPE)
    gemm_mma<3><<<dim3(ND/128, NM/128, 3), 256, GEMM_DYNSMEM>>>(
        a1, a2, b1, b2, nullptr, NM, ND, ND);

    // attention writes LN(SiLU(O)) bf16 splits directly into g_a1/g_a2
    attn_mma_kernel<<<dim3(NS/128, NH, NB), 256, ATTN_SMEM>>>(lnw, lnb);

    split_kernel<<<wsplit, 256>>>(Wo, b1, b2, ND*ND);
    gemm_mma<0><<<dim3(ND/128, NM/128), 256, GEMM_DYNSMEM>>>(
        a1, a2, b1, b2, out, NM, ND, ND);
}

// round 11
// speedup vs baseline: 1.0007x; 1.0006x over previous
#include <cuda_runtime.h>
#include <cuda_bf16.h>
#include <math.h>
#include <stdint.h>

// Problem constants
#define NB 4
#define NS 2048
#define ND 1024
#define NH 16
#define HD 64
#define NM (NB*NS)          // 8192 rows

// ---------------- scratch (device globals: no allocation allowed) ----------
__device__ float g_sin[NS*(HD/2)];
__device__ float g_cos[NS*(HD/2)];
// bf16 split buffers
__device__ __nv_bfloat16 g_q1[(size_t)NM*ND];
__device__ __nv_bfloat16 g_q2[(size_t)NM*ND];
__device__ __nv_bfloat16 g_k1[(size_t)NM*ND];
__device__ __nv_bfloat16 g_k2[(size_t)NM*ND];
__device__ __nv_bfloat16 g_v1[(size_t)NM*ND];
__device__ __nv_bfloat16 g_v2[(size_t)NM*ND];
__device__ __nv_bfloat16 g_a1[(size_t)NM*ND];
__device__ __nv_bfloat16 g_a2[(size_t)NM*ND];
__device__ __nv_bfloat16 g_b1[(size_t)3*ND*ND];
__device__ __nv_bfloat16 g_b2[(size_t)3*ND*ND];

// ---------------- helpers ----------------------------------------------------
static __device__ __forceinline__ uint32_t smem_u32(const void* p) {
    uint32_t a;
    asm("{ .reg .u64 t; cvta.to.shared.u64 t, %1; cvt.u32.u64 %0, t; }"
        : "=r"(a) : "l"(p));
    return a;
}
static __device__ __forceinline__ uint32_t packbf2(float lo, float hi) {
    __nv_bfloat162 t = __floats2bfloat162_rn(lo, hi);
    return *(uint32_t*)&t;
}

#define LDSM4(d, addr) \
    asm volatile("ldmatrix.sync.aligned.m8n8.x4.shared.b16 {%0,%1,%2,%3}, [%4];" \
                 : "=r"((d)[0]), "=r"((d)[1]), "=r"((d)[2]), "=r"((d)[3]) : "r"(addr))
#define LDSM4T(d, addr) \
    asm volatile("ldmatrix.sync.aligned.m8n8.x4.trans.shared.b16 {%0,%1,%2,%3}, [%4];" \
                 : "=r"((d)[0]), "=r"((d)[1]), "=r"((d)[2]), "=r"((d)[3]) : "r"(addr))

#define MMA16816(c, a, b0, b1) \
    asm volatile("mma.sync.aligned.m16n8k16.row.col.f32.bf16.bf16.f32 " \
                 "{%0,%1,%2,%3}, {%4,%5,%6,%7}, {%8,%9}, {%0,%1,%2,%3};" \
                 : "+f"((c)[0]), "+f"((c)[1]), "+f"((c)[2]), "+f"((c)[3]) \
                 : "r"((a)[0]), "r"((a)[1]), "r"((a)[2]), "r"((a)[3]), \
                   "r"(b0), "r"(b1))

#define CP16(dst, src) \
    asm volatile("cp.async.cg.shared.global [%0], [%1], 16;" :: "r"(dst), "l"(src))

// ---------------- trig tables ------------------------------------------------
__global__ void trig_kernel() {
    int i = blockIdx.x*blockDim.x + threadIdx.x;
    if (i >= NS*(HD/2)) return;
    int pos = i >> 5;
    int j   = i & 31;
    double angle = exp(-((double)j/31.0)*log(10000.0));
    double arg = (double)pos * angle;
    g_sin[i] = (float)sin(arg);
    g_cos[i] = (float)cos(arg);
}

// ---------------- fp32 -> (bf16 hi, bf16 lo) split --------------------------
static __device__ __forceinline__ void split4(const float* __restrict__ src,
                                              __nv_bfloat16* __restrict__ d1,
                                              __nv_bfloat16* __restrict__ d2,
                                              size_t i) {
    float4 v = *(const float4*)(src + i);
    float a0=v.x, a1=v.y, a2=v.z, a3=v.w;
    __nv_bfloat16 h0=__float2bfloat16(a0), h1=__float2bfloat16(a1),
                  h2=__float2bfloat16(a2), h3=__float2bfloat16(a3);
    ushort4 u1, u2;
    u1.x=__bfloat16_as_ushort(h0); u1.y=__bfloat16_as_ushort(h1);
    u1.z=__bfloat16_as_ushort(h2); u1.w=__bfloat16_as_ushort(h3);
    u2.x=__bfloat16_as_ushort(__float2bfloat16(a0-__bfloat162float(h0)));
    u2.y=__bfloat16_as_ushort(__float2bfloat16(a1-__bfloat162float(h1)));
    u2.z=__bfloat16_as_ushort(__float2bfloat16(a2-__bfloat162float(h2)));
    u2.w=__bfloat16_as_ushort(__float2bfloat16(a3-__bfloat162float(h3)));
    *(ushort4*)(d1 + i) = u1;
    *(ushort4*)(d2 + i) = u2;
}

__global__ __launch_bounds__(256)
void split_kernel(const float* __restrict__ src,
                  __nv_bfloat16* __restrict__ d1,
                  __nv_bfloat16* __restrict__ d2, int n) {
    size_t i = ((size_t)blockIdx.x*blockDim.x + threadIdx.x) * 4;
    if (i >= (size_t)n) return;
    split4(src, d1, d2, i);
}

// three weights -> concatenated split buffers, one launch
__global__ __launch_bounds__(256)
void split3_kernel(const float* __restrict__ w0, const float* __restrict__ w1,
                   const float* __restrict__ w2) {
    int seg = blockIdx.y;
    size_t i = ((size_t)blockIdx.x*blockDim.x + threadIdx.x) * 4;
    if (i >= (size_t)ND*ND) return;
    const float* src = (seg==0) ? w0 : (seg==1) ? w1 : w2;
    split4(src, g_b1 + (size_t)seg*ND*ND, g_b2 + (size_t)seg*ND*ND, i);
}

// ---------------- HMMA bf16x3 GEMM: C = A @ B^T, 2-stage (R4 config) --------
// MODE 0: write fp32 C.  MODE 3: fused QKV (z selects weight slice + output,
//         z<2 applies RoPE before split).
#define GT_LDB   80            // bytes per smem row (40 bf16)
#define GT_TILE  (128*GT_LDB)  // 10240
#define GT_STAGE (4*GT_TILE)   // 40960
#define GEMM_DYNSMEM (2*GT_STAGE)

template<int MODE>
__global__ __launch_bounds__(256, 2)
void gemm_mma(const __nv_bfloat16* __restrict__ A1, const __nv_bfloat16* __restrict__ A2,
              const __nv_bfloat16* __restrict__ B1, const __nv_bfloat16* __restrict__ B2,
              float* __restrict__ C, int M, int N, int K)
{
    extern __shared__ char dsm[];
    uint32_t smb = smem_u32(dsm);
    int tid = threadIdx.x, lane = tid & 31, wid = tid >> 5;
    int wm = wid & 1, wn = wid >> 1;           // 2x4 warp grid
    int m0 = blockIdx.y * 128, n0 = blockIdx.x * 128;
    int z = (MODE == 3) ? blockIdx.z : 0;
    size_t wslice = (size_t)z * ND * ND;

    const __nv_bfloat16* pa1 = A1 + (size_t)m0 * K;
    const __nv_bfloat16* pa2 = A2 + (size_t)m0 * K;
    const __nv_bfloat16* pb1 = B1 + wslice + (size_t)n0 * K;
    const __nv_bfloat16* pb2 = B2 + wslice + (size_t)n0 * K;

    int v0r = tid >> 2,          v0c = tid & 3;
    int v1r = (tid + 256) >> 2,  v1c = tid & 3;

    int q = lane >> 3, r = lane & 7;
    uint32_t aoff = (uint32_t)((wm*64 + r + 8*(q & 1)) * GT_LDB + 16*(q >> 1));
    uint32_t boff = (uint32_t)((wn*32 + r + 8*(q >> 1)) * GT_LDB + 16*(q & 1));

    float acc[4][4][4] = {};

    int nk = K / 32;
#define LOAD_STAGE(s, k0)                                                        \
    {                                                                            \
        uint32_t st = smb + ((s) & 1) * GT_STAGE;                                \
        uint32_t o0 = (uint32_t)(v0r * GT_LDB + v0c * 16);                       \
        uint32_t o1 = (uint32_t)(v1r * GT_LDB + v1c * 16);                       \
        size_t g0 = (size_t)v0r * K + (k0) + v0c * 8;                            \
        size_t g1 = (size_t)v1r * K + (k0) + v1c * 8;                            \
        CP16(st + o0,             pa1 + g0);  CP16(st + o1,             pa1 + g1);\
        CP16(st + GT_TILE   + o0, pa2 + g0);  CP16(st + GT_TILE   + o1, pa2 + g1);\
        CP16(st + 2*GT_TILE + o0, pb1 + g0);  CP16(st + 2*GT_TILE + o1, pb1 + g1);\
        CP16(st + 3*GT_TILE + o0, pb2 + g0);  CP16(st + 3*GT_TILE + o1, pb2 + g1);\
        asm volatile("cp.async.commit_group;");                                  \
    }

    LOAD_STAGE(0, 0)
    asm volatile("cp.async.wait_group 0;");
    __syncthreads();

    for (int s = 0; s < nk; s++) {
        if (s + 1 < nk) LOAD_STAGE(s + 1, (s + 1) * 32)
        uint32_t st = smb + (s & 1) * GT_STAGE;
#pragma unroll
        for (int kk = 0; kk < 2; kk++) {
            uint32_t ka = st + aoff + kk*32;
            uint32_t kb = st + boff + kk*32;
            uint32_t a1f[4][4], a2f[4][4], bfr[2][4];
#pragma unroll
            for (int i = 0; i < 4; i++) LDSM4(a1f[i], ka + i*16*GT_LDB);
#pragma unroll
            for (int i = 0; i < 4; i++) LDSM4(a2f[i], ka + GT_TILE + i*16*GT_LDB);
#pragma unroll
            for (int j = 0; j < 2; j++) LDSM4(bfr[j], kb + 2*GT_TILE + j*16*GT_LDB);
#pragma unroll
            for (int i = 0; i < 4; i++)
#pragma unroll
                for (int jj = 0; jj < 4; jj++)
                    MMA16816(acc[i][jj], a1f[i], bfr[jj>>1][(jj&1)*2], bfr[jj>>1][(jj&1)*2+1]);
#pragma unroll
            for (int i = 0; i < 4; i++)
#pragma unroll
                for (int jj = 0; jj < 4; jj++)
                    MMA16816(acc[i][jj], a2f[i], bfr[jj>>1][(jj&1)*2], bfr[jj>>1][(jj&1)*2+1]);
#pragma unroll
            for (int j = 0; j < 2; j++) LDSM4(bfr[j], kb + 3*GT_TILE + j*16*GT_LDB);
#pragma unroll
            for (int i = 0; i < 4; i++)
#pragma unroll
                for (int jj = 0; jj < 4; jj++)
                    MMA16816(acc[i][jj], a1f[i], bfr[jj>>1][(jj&1)*2], bfr[jj>>1][(jj&1)*2+1]);
        }
        if (s + 1 < nk) asm volatile("cp.async.wait_group 0;");
        __syncthreads();
    }

    // epilogue
    int mrow = m0 + wm*64 + (lane >> 2);
    int ncol = n0 + wn*32 + (lane & 3)*2;
    __nv_bfloat16 *C1 = nullptr, *C2 = nullptr;
    if (MODE == 3) {
        C1 = (z==0) ? g_q1 : (z==1) ? g_k1 : g_v1;
        C2 = (z==0) ? g_q2 : (z==1) ? g_k2 : g_v2;
    }
#pragma unroll
    for (int i = 0; i < 4; i++) {
#pragma unroll
        for (int jj = 0; jj < 4; jj++) {
            if (MODE == 0) {
                *(float2*)(C + (size_t)(mrow + i*16)     * N + ncol + jj*8) =
                    make_float2(acc[i][jj][0], acc[i][jj][1]);
                *(float2*)(C + (size_t)(mrow + i*16 + 8) * N + ncol + jj*8) =
                    make_float2(acc[i][jj][2], acc[i][jj][3]);
            } else {
                int col = ncol + jj*8;
#pragma unroll
                for (int half = 0; half < 2; half++) {
                    int row = mrow + i*16 + half*8;
                    float c0 = acc[i][jj][half*2], c1 = acc[i][jj][half*2+1];
                    float y0 = c0, y1 = c1;
                    if (z < 2) {   // RoPE for q, k
                        int pos = row & (NS-1);
                        int j = (col & 63) >> 1;
                        float sn = g_sin[pos*32 + j], cs = g_cos[pos*32 + j];
                        y0 = c0*cs - c1*sn;
                        y1 = c1*cs + c0*sn;
                    }
                    __nv_bfloat16 h0 = __float2bfloat16(y0), h1 = __float2bfloat16(y1);
                    uint32_t u1 = (uint32_t)__bfloat16_as_ushort(h0) |
                                  ((uint32_t)__bfloat16_as_ushort(h1) << 16);
                    uint32_t u2 = packbf2(y0 - __bfloat162float(h0),
                                          y1 - __bfloat162float(h1));
                    *(uint32_t*)(C1 + (size_t)row * N + col) = u1;
                    *(uint32_t*)(C2 + (size_t)row * N + col) = u2;
                }
            }
        }
    }
}

// ---------------- attention: HMMA bf16x3, causal decay mask -----------------
// block: 128 q-rows of one (b,h); 8 warps x 16 rows. t-tiles of 64 rows,
// K/V double-buffered. S stays in registers. Epilogue fuses LN+SiLU+split.
#define AT_LDB    144                        // smem row stride (bytes)
#define AT_Q1     0
#define AT_Q2     (128*AT_LDB)               // 18432
#define AT_STAGE0 (2*128*AT_LDB)             // 36864
#define AT_KTILE  (64*AT_LDB)                // 9216
#define AT_STAGE_SZ (4*AT_KTILE)             // 36864
#define ATTN_SMEM (AT_STAGE0 + 2*AT_STAGE_SZ)  // 110592

__global__ __launch_bounds__(256)
void attn_mma_kernel(const float* __restrict__ lnw, const float* __restrict__ lnb) {
    extern __shared__ char smc[];
    uint32_t smb = smem_u32(smc);
    int tid = threadIdx.x, lane = tid & 31, wid = tid >> 5;
    int qb = (int)(gridDim.x - 1 - blockIdx.x);   // heavy blocks first
    int h = blockIdx.y, bb = blockIdx.z;
    int q0 = qb * 128;
    size_t rowbase = (size_t)bb * NS;
    size_t headoff = (size_t)h * HD;
    float dec = (float)log(1.0 - exp2(-5.0 - (double)h));   // negative

    // ---- load Q tile (both splits) ----
#pragma unroll
    for (int it = 0; it < 8; it++) {
        int idx = tid + it*256;               // 0..2047
        int t  = idx >> 10;                   // 0:q1 1:q2
        int rr = (idx >> 3) & 127;
        int cc = idx & 7;
        const __nv_bfloat16* src = (t ? g_q2 : g_q1) +
            (rowbase + q0 + rr)*ND + headoff + cc*8;
        uint32_t dst = smb + (t ? AT_Q2 : AT_Q1) + rr*AT_LDB + cc*16;
        CP16(dst, src);
    }

#define AT_LOAD(stage, t0_)                                                    \
    {                                                                          \
        uint32_t stb = smb + AT_STAGE0 + (stage)*AT_STAGE_SZ;                  \
        _Pragma("unroll")                                                      \
        for (int it = 0; it < 8; it++) {                                       \
            int idx = tid + it*256;                                            \
            int ts = idx >> 9;                                                 \
            int rr = (idx >> 3) & 63;                                          \
            int cc = idx & 7;                                                  \
            const __nv_bfloat16* sp =                                          \
                (ts==0 ? g_k1 : ts==1 ? g_k2 : ts==2 ? g_v1 : g_v2) +          \
                (rowbase + (t0_) + rr)*ND + headoff + cc*8;                    \
            CP16(stb + ts*AT_KTILE + rr*AT_LDB + cc*16, sp);                   \
        }                                                                      \
        asm volatile("cp.async.commit_group;");                                \
    }

    AT_LOAD(0, 0)
    asm volatile("cp.async.wait_group 0;");
    __syncthreads();

    int wr = wid * 16;
    int qlo = lane >> 2;                      // 0..7 row within 8
    uint32_t aoff = (uint32_t)((wr + (lane & 7) + 8*((lane >> 3) & 1))*AT_LDB
                               + 16*(lane >> 4));
    uint32_t boff = (uint32_t)(((lane & 7) + 8*((lane >> 3) >> 1))*AT_LDB
                               + 16*((lane >> 3) & 1));
    uint32_t voff = (uint32_t)((lane & 15)*AT_LDB + 16*(lane >> 4));

    float oacc[8][4] = {};
    float mul8 = __expf(dec * 8.0f);
    int ntt = 2*qb + 2;

    for (int tt = 0; tt < ntt; tt++) {
        int t0 = tt * 64;
        if (tt + 1 < ntt) AT_LOAD((tt+1) & 1, (tt+1)*64)

        uint32_t stb = smb + AT_STAGE0 + (tt & 1)*AT_STAGE_SZ;
        bool active = (q0 + wr + 15) >= t0;
        if (active) {
            // ---- S = Q K^T (bf16x3) ----
            float s[8][4] = {};
#pragma unroll
            for (int kk = 0; kk < 4; kk++) {
                uint32_t a1f[4], a2f[4];
                LDSM4(a1f, smb + AT_Q1 + aoff + kk*32);
                LDSM4(a2f, smb + AT_Q2 + aoff + kk*32);
#pragma unroll
                for (int nc = 0; nc < 4; nc++) {
                    uint32_t f1[4], f2[4];
                    LDSM4(f1, stb + boff + nc*16*AT_LDB + kk*32);
                    LDSM4(f2, stb + AT_KTILE + boff + nc*16*AT_LDB + kk*32);
                    MMA16816(s[2*nc],   a1f, f1[0], f1[1]);
                    MMA16816(s[2*nc+1], a1f, f1[2], f1[3]);
                    MMA16816(s[2*nc],   a2f, f1[0], f1[1]);
                    MMA16816(s[2*nc+1], a2f, f1[2], f1[3]);
                    MMA16816(s[2*nc],   a1f, f2[0], f2[1]);
                    MMA16816(s[2*nc+1], a1f, f2[2], f2[3]);
                }
            }
            // ---- decay mask (factored) + causal ----
            float rowf0 = __expf(dec * (float)(q0 + wr + qlo - t0));
            float rowf1 = rowf0 * mul8;
            float colf[8][2];
#pragma unroll
            for (int nt = 0; nt < 8; nt++)
#pragma unroll
                for (int par = 0; par < 2; par++)
                    colf[nt][par] = __expf(-dec * (float)(nt*8 + (lane&3)*2 + par));
            bool needcmp = (q0 + wr) < (t0 + 63);
#pragma unroll
            for (int nt = 0; nt < 8; nt++)
#pragma unroll
                for (int e = 0; e < 4; e++) {
                    int rloc = qlo + ((e >= 2) ? 8 : 0);
                    int cloc = nt*8 + (lane&3)*2 + (e & 1);
                    float m = ((e >= 2) ? rowf1 : rowf0) * colf[nt][e & 1];
                    if (needcmp && (q0 + wr + rloc) < (t0 + cloc)) m = 0.f;
                    s[nt][e] *= m;
                }
            // ---- split S in-register, O += S V (bf16x3) ----
#pragma unroll
            for (int kt = 0; kt < 4; kt++) {
                uint32_t sp1[4], sp2[4];
#pragma unroll
                for (int j = 0; j < 4; j++) {
                    int nt = 2*kt + (j >> 1);
                    int e0 = (j & 1) * 2;
                    float x0 = s[nt][e0], x1 = s[nt][e0+1];
                    __nv_bfloat16 h0 = __float2bfloat16(x0), h1 = __float2bfloat16(x1);
                    sp1[j] = (uint32_t)__bfloat16_as_ushort(h0) |
                             ((uint32_t)__bfloat16_as_ushort(h1) << 16);
                    sp2[j] = packbf2(x0 - __bfloat162float(h0),
                                     x1 - __bfloat162float(h1));
                }
#pragma unroll
                for (int nv = 0; nv < 4; nv++) {
                    uint32_t f1[4], f2[4];
                    LDSM4T(f1, stb + 2*AT_KTILE + voff + kt*16*AT_LDB + nv*32);
                    LDSM4T(f2, stb + 3*AT_KTILE + voff + kt*16*AT_LDB + nv*32);
                    MMA16816(oacc[2*nv],   sp1, f1[0], f1[1]);
                    MMA16816(oacc[2*nv+1], sp1, f1[2], f1[3]);
                    MMA16816(oacc[2*nv],   sp2, f1[0], f1[1]);
                    MMA16816(oacc[2*nv+1], sp2, f1[2], f1[3]);
                    MMA16816(oacc[2*nv],   sp1, f2[0], f2[1]);
                    MMA16816(oacc[2*nv+1], sp1, f2[2], f2[3]);
                }
            }
        }
        if (tt + 1 < ntt) asm volatile("cp.async.wait_group 0;");
        __syncthreads();
    }

    // ---- fused LayerNorm(64) + SiLU + bf16 split, write to g_a1/g_a2 ----
    int colbase = (lane & 3)*2;
#pragma unroll
    for (int half = 0; half < 2; half++) {
        float sum = 0.f, sq = 0.f;
#pragma unroll
        for (int nt = 0; nt < 8; nt++) {
            float v0 = oacc[nt][half*2], v1 = oacc[nt][half*2+1];
            sum += v0 + v1;
            sq  += v0*v0 + v1*v1;
        }
        sum += __shfl_xor_sync(0xffffffffu, sum, 1);
        sq  += __shfl_xor_sync(0xffffffffu, sq, 1);
        sum += __shfl_xor_sync(0xffffffffu, sum, 2);
        sq  += __shfl_xor_sync(0xffffffffu, sq, 2);
        float mean = sum * (1.f/64.f);
        float var  = sq * (1.f/64.f) - mean*mean;
        float rs = rsqrtf(var + 1e-5f);
        size_t rbase = (rowbase + q0 + wr + qlo + half*8)*ND + headoff;
#pragma unroll
        for (int nt = 0; nt < 8; nt++) {
            int c = nt*8 + colbase;
            float y0 = (oacc[nt][half*2]   - mean)*rs*lnw[c]   + lnb[c];
            float y1 = (oacc[nt][half*2+1] - mean)*rs*lnw[c+1] + lnb[c+1];
            y0 = y0 / (1.f + __expf(-y0));
            y1 = y1 / (1.f + __expf(-y1));
            __nv_bfloat16 h0 = __float2bfloat16(y0), h1 = __float2bfloat16(y1);
            uint32_t u1 = (uint32_t)__bfloat16_as_ushort(h0) |
                          ((uint32_t)__bfloat16_as_ushort(h1) << 16);
            uint32_t u2 = packbf2(y0 - __bfloat162float(h0),
                                  y1 - __bfloat162float(h1));
            *(uint32_t*)(g_a1 + rbase + c) = u1;
            *(uint32_t*)(g_a2 + rbase + c) = u2;
        }
    }
}

// ---------------- launcher ---------------------------------------------------
extern "C" void kernel_launch(void* const* d_in, const int* in_sizes, int n_in,
                              void* d_out, int out_size) {
    const float* x   = (const float*)d_in[0];
    const float* Wq  = (const float*)d_in[1];
    const float* Wk  = (const float*)d_in[2];
    const float* Wv  = (const float*)d_in[3];
    const float* Wo  = (const float*)d_in[4];
    const float* lnw = (const float*)d_in[5];
    const float* lnb = (const float*)d_in[6];
    float* out = (float*)d_out;

    __nv_bfloat16 *a1, *a2, *b1, *b2;
    cudaGetSymbolAddress((void**)&a1, g_a1);
    cudaGetSymbolAddress((void**)&a2, g_a2);
    cudaGetSymbolAddress((void**)&b1, g_b1);
    cudaGetSymbolAddress((void**)&b2, g_b2);

    trig_kernel<<<(NS*(HD/2)+255)/256, 256>>>();

    cudaFuncSetAttribute(gemm_mma<0>, cudaFuncAttributeMaxDynamicSharedMemorySize, GEMM_DYNSMEM);
    cudaFuncSetAttribute(gemm_mma<3>, cudaFuncAttributeMaxDynamicSharedMemorySize, GEMM_DYNSMEM);
    cudaFuncSetAttribute(attn_mma_kernel, cudaFuncAttributeMaxDynamicSharedMemorySize, ATTN_SMEM);

    dim3 wsplit((ND*ND/4 + 255)/256);
    dim3 asplit(((size_t)NM*ND/4 + 255)/256);

    // split activations (x) and all three weights
    split_kernel<<<asplit, 256>>>(x, a1, a2, NM*ND);
    split3_kernel<<<dim3(ND*ND/4/256, 3), 256>>>(Wq, Wk, Wv);

    // fused QKV projection: one launch, grid.z selects weight + output (+RoPE)
    gemm_mma<3><<<dim3(ND/128, NM/128, 3), 256, GEMM_DYNSMEM>>>(
        a1, a2, b1, b2, nullptr, NM, ND, ND);

    // attention writes LN(SiLU(O)) bf16 splits directly into g_a1/g_a2
    attn_mma_kernel<<<dim3(NS/128, NH, NB), 256, ATTN_SMEM>>>(lnw, lnb);

    split_kernel<<<wsplit, 256>>>(Wo, b1, b2, ND*ND);
    gemm_mma<0><<<dim3(ND/128, NM/128), 256, GEMM_DYNSMEM>>>(
        a1, a2, b1, b2, out, NM, ND, ND);
}

// round 12
// speedup vs baseline: 1.0010x; 1.0002x over previous
#include <cuda_runtime.h>
#include <cuda_bf16.h>
#include <math.h>
#include <stdint.h>

// Problem constants
#define NB 4
#define NS 2048
#define ND 1024
#define NH 16
#define HD 64
#define NM (NB*NS)          // 8192 rows

// ---------------- scratch (device globals: no allocation allowed) ----------
__device__ float g_sin[NS*(HD/2)];
__device__ float g_cos[NS*(HD/2)];
// bf16 split buffers
__device__ __nv_bfloat16 g_q1[(size_t)NM*ND];
__device__ __nv_bfloat16 g_q2[(size_t)NM*ND];
__device__ __nv_bfloat16 g_k1[(size_t)NM*ND];
__device__ __nv_bfloat16 g_k2[(size_t)NM*ND];
__device__ __nv_bfloat16 g_v1[(size_t)NM*ND];
__device__ __nv_bfloat16 g_v2[(size_t)NM*ND];
__device__ __nv_bfloat16 g_a1[(size_t)NM*ND];
__device__ __nv_bfloat16 g_a2[(size_t)NM*ND];
__device__ __nv_bfloat16 g_b1[(size_t)3*ND*ND];
__device__ __nv_bfloat16 g_b2[(size_t)3*ND*ND];

// ---------------- helpers ----------------------------------------------------
static __device__ __forceinline__ uint32_t smem_u32(const void* p) {
    uint32_t a;
    asm("{ .reg .u64 t; cvta.to.shared.u64 t, %1; cvt.u32.u64 %0, t; }"
        : "=r"(a) : "l"(p));
    return a;
}
static __device__ __forceinline__ uint32_t packbf2(float lo, float hi) {
    __nv_bfloat162 t = __floats2bfloat162_rn(lo, hi);
    return *(uint32_t*)&t;
}

#define LDSM4(d, addr) \
    asm volatile("ldmatrix.sync.aligned.m8n8.x4.shared.b16 {%0,%1,%2,%3}, [%4];" \
                 : "=r"((d)[0]), "=r"((d)[1]), "=r"((d)[2]), "=r"((d)[3]) : "r"(addr))
#define LDSM4T(d, addr) \
    asm volatile("ldmatrix.sync.aligned.m8n8.x4.trans.shared.b16 {%0,%1,%2,%3}, [%4];" \
                 : "=r"((d)[0]), "=r"((d)[1]), "=r"((d)[2]), "=r"((d)[3]) : "r"(addr))

#define MMA16816(c, a, b0, b1) \
    asm volatile("mma.sync.aligned.m16n8k16.row.col.f32.bf16.bf16.f32 " \
                 "{%0,%1,%2,%3}, {%4,%5,%6,%7}, {%8,%9}, {%0,%1,%2,%3};" \
                 : "+f"((c)[0]), "+f"((c)[1]), "+f"((c)[2]), "+f"((c)[3]) \
                 : "r"((a)[0]), "r"((a)[1]), "r"((a)[2]), "r"((a)[3]), \
                   "r"(b0), "r"(b1))

#define CP16(dst, src) \
    asm volatile("cp.async.cg.shared.global [%0], [%1], 16;" :: "r"(dst), "l"(src))

// ---------------- trig tables ------------------------------------------------
__global__ void trig_kernel() {
    int i = blockIdx.x*blockDim.x + threadIdx.x;
    if (i >= NS*(HD/2)) return;
    int pos = i >> 5;
    int j   = i & 31;
    double angle = exp(-((double)j/31.0)*log(10000.0));
    double arg = (double)pos * angle;
    g_sin[i] = (float)sin(arg);
    g_cos[i] = (float)cos(arg);
}

// ---------------- fp32 -> (bf16 hi, bf16 lo) split --------------------------
static __device__ __forceinline__ void split4(const float* __restrict__ src,
                                              __nv_bfloat16* __restrict__ d1,
                                              __nv_bfloat16* __restrict__ d2,
                                              size_t i) {
    float4 v = *(const float4*)(src + i);
    float a0=v.x, a1=v.y, a2=v.z, a3=v.w;
    __nv_bfloat16 h0=__float2bfloat16(a0), h1=__float2bfloat16(a1),
                  h2=__float2bfloat16(a2), h3=__float2bfloat16(a3);
    ushort4 u1, u2;
    u1.x=__bfloat16_as_ushort(h0); u1.y=__bfloat16_as_ushort(h1);
    u1.z=__bfloat16_as_ushort(h2); u1.w=__bfloat16_as_ushort(h3);
    u2.x=__bfloat16_as_ushort(__float2bfloat16(a0-__bfloat162float(h0)));
    u2.y=__bfloat16_as_ushort(__float2bfloat16(a1-__bfloat162float(h1)));
    u2.z=__bfloat16_as_ushort(__float2bfloat16(a2-__bfloat162float(h2)));
    u2.w=__bfloat16_as_ushort(__float2bfloat16(a3-__bfloat162float(h3)));
    *(ushort4*)(d1 + i) = u1;
    *(ushort4*)(d2 + i) = u2;
}

__global__ __launch_bounds__(256)
void split_kernel(const float* __restrict__ src,
                  __nv_bfloat16* __restrict__ d1,
                  __nv_bfloat16* __restrict__ d2, int n) {
    size_t i = ((size_t)blockIdx.x*blockDim.x + threadIdx.x) * 4;
    if (i >= (size_t)n) return;
    split4(src, d1, d2, i);
}

// three weights -> concatenated split buffers, one launch
__global__ __launch_bounds__(256)
void split3_kernel(const float* __restrict__ w0, const float* __restrict__ w1,
                   const float* __restrict__ w2) {
    int seg = blockIdx.y;
    size_t i = ((size_t)blockIdx.x*blockDim.x + threadIdx.x) * 4;
    if (i >= (size_t)ND*ND) return;
    const float* src = (seg==0) ? w0 : (seg==1) ? w1 : w2;
    split4(src, g_b1 + (size_t)seg*ND*ND, g_b2 + (size_t)seg*ND*ND, i);
}

// ---------------- HMMA bf16x3 GEMM: C = A @ B^T, 2-stage (R4 config) --------
// MODE 0: write fp32 C.  MODE 3: fused QKV (z selects weight slice + output,
//         z<2 applies RoPE before split).
#define GT_LDB   80            // bytes per smem row (40 bf16)
#define GT_TILE  (128*GT_LDB)  // 10240
#define GT_STAGE (4*GT_TILE)   // 40960
#define GEMM_DYNSMEM (2*GT_STAGE)

template<int MODE>
__global__ __launch_bounds__(256, 2)
void gemm_mma(const __nv_bfloat16* __restrict__ A1, const __nv_bfloat16* __restrict__ A2,
              const __nv_bfloat16* __restrict__ B1, const __nv_bfloat16* __restrict__ B2,
              float* __restrict__ C, int M, int N, int K)
{
    extern __shared__ char dsm[];
    uint32_t smb = smem_u32(dsm);
    int tid = threadIdx.x, lane = tid & 31, wid = tid >> 5;
    int wm = wid & 1, wn = wid >> 1;           // 2x4 warp grid
    int m0 = blockIdx.y * 128, n0 = blockIdx.x * 128;
    int z = (MODE == 3) ? blockIdx.z : 0;
    size_t wslice = (size_t)z * ND * ND;

    const __nv_bfloat16* pa1 = A1 + (size_t)m0 * K;
    const __nv_bfloat16* pa2 = A2 + (size_t)m0 * K;
    const __nv_bfloat16* pb1 = B1 + wslice + (size_t)n0 * K;
    const __nv_bfloat16* pb2 = B2 + wslice + (size_t)n0 * K;

    int v0r = tid >> 2,          v0c = tid & 3;
    int v1r = (tid + 256) >> 2,  v1c = tid & 3;

    int q = lane >> 3, r = lane & 7;
    uint32_t aoff = (uint32_t)((wm*64 + r + 8*(q & 1)) * GT_LDB + 16*(q >> 1));
    uint32_t boff = (uint32_t)((wn*32 + r + 8*(q >> 1)) * GT_LDB + 16*(q & 1));

    float acc[4][4][4] = {};

    int nk = K / 32;
#define LOAD_STAGE(s, k0)                                                        \
    {                                                                            \
        uint32_t st = smb + ((s) & 1) * GT_STAGE;                                \
        uint32_t o0 = (uint32_t)(v0r * GT_LDB + v0c * 16);                       \
        uint32_t o1 = (uint32_t)(v1r * GT_LDB + v1c * 16);                       \
        size_t g0 = (size_t)v0r * K + (k0) + v0c * 8;                            \
        size_t g1 = (size_t)v1r * K + (k0) + v1c * 8;                            \
        CP16(st + o0,             pa1 + g0);  CP16(st + o1,             pa1 + g1);\
        CP16(st + GT_TILE   + o0, pa2 + g0);  CP16(st + GT_TILE   + o1, pa2 + g1);\
        CP16(st + 2*GT_TILE + o0, pb1 + g0);  CP16(st + 2*GT_TILE + o1, pb1 + g1);\
        CP16(st + 3*GT_TILE + o0, pb2 + g0);  CP16(st + 3*GT_TILE + o1, pb2 + g1);\
        asm volatile("cp.async.commit_group;");                                  \
    }

    LOAD_STAGE(0, 0)
    asm volatile("cp.async.wait_group 0;");
    __syncthreads();

    for (int s = 0; s < nk; s++) {
        if (s + 1 < nk) LOAD_STAGE(s + 1, (s + 1) * 32)
        uint32_t st = smb + (s & 1) * GT_STAGE;
#pragma unroll
        for (int kk = 0; kk < 2; kk++) {
            uint32_t ka = st + aoff + kk*32;
            uint32_t kb = st + boff + kk*32;
            uint32_t a1f[4][4], a2f[4][4], bfr[2][4];
#pragma unroll
            for (int i = 0; i < 4; i++) LDSM4(a1f[i], ka + i*16*GT_LDB);
#pragma unroll
            for (int i = 0; i < 4; i++) LDSM4(a2f[i], ka + GT_TILE + i*16*GT_LDB);
#pragma unroll
            for (int j = 0; j < 2; j++) LDSM4(bfr[j], kb + 2*GT_TILE + j*16*GT_LDB);
#pragma unroll
            for (int i = 0; i < 4; i++)
#pragma unroll
                for (int jj = 0; jj < 4; jj++)
                    MMA16816(acc[i][jj], a1f[i], bfr[jj>>1][(jj&1)*2], bfr[jj>>1][(jj&1)*2+1]);
#pragma unroll
            for (int i = 0; i < 4; i++)
#pragma unroll
                for (int jj = 0; jj < 4; jj++)
                    MMA16816(acc[i][jj], a2f[i], bfr[jj>>1][(jj&1)*2], bfr[jj>>1][(jj&1)*2+1]);
#pragma unroll
            for (int j = 0; j < 2; j++) LDSM4(bfr[j], kb + 3*GT_TILE + j*16*GT_LDB);
#pragma unroll
            for (int i = 0; i < 4; i++)
#pragma unroll
                for (int jj = 0; jj < 4; jj++)
                    MMA16816(acc[i][jj], a1f[i], bfr[jj>>1][(jj&1)*2], bfr[jj>>1][(jj&1)*2+1]);
        }
        if (s + 1 < nk) asm volatile("cp.async.wait_group 0;");
        __syncthreads();
    }

    // epilogue
    int mrow = m0 + wm*64 + (lane >> 2);
    int ncol = n0 + wn*32 + (lane & 3)*2;
    __nv_bfloat16 *C1 = nullptr, *C2 = nullptr;
    if (MODE == 3) {
        C1 = (z==0) ? g_q1 : (z==1) ? g_k1 : g_v1;
        C2 = (z==0) ? g_q2 : (z==1) ? g_k2 : g_v2;
    }
#pragma unroll
    for (int i = 0; i < 4; i++) {
#pragma unroll
        for (int jj = 0; jj < 4; jj++) {
            if (MODE == 0) {
                *(float2*)(C + (size_t)(mrow + i*16)     * N + ncol + jj*8) =
                    make_float2(acc[i][jj][0], acc[i][jj][1]);
                *(float2*)(C + (size_t)(mrow + i*16 + 8) * N + ncol + jj*8) =
                    make_float2(acc[i][jj][2], acc[i][jj][3]);
            } else {
                int col = ncol + jj*8;
#pragma unroll
                for (int half = 0; half < 2; half++) {
                    int row = mrow + i*16 + half*8;
                    float c0 = acc[i][jj][half*2], c1 = acc[i][jj][half*2+1];
                    float y0 = c0, y1 = c1;
                    if (z < 2) {   // RoPE for q, k
                        int pos = row & (NS-1);
                        int j = (col & 63) >> 1;
                        float sn = g_sin[pos*32 + j], cs = g_cos[pos*32 + j];
                        y0 = c0*cs - c1*sn;
                        y1 = c1*cs + c0*sn;
                    }
                    __nv_bfloat16 h0 = __float2bfloat16(y0), h1 = __float2bfloat16(y1);
                    uint32_t u1 = (uint32_t)__bfloat16_as_ushort(h0) |
                                  ((uint32_t)__bfloat16_as_ushort(h1) << 16);
                    uint32_t u2 = packbf2(y0 - __bfloat162float(h0),
                                          y1 - __bfloat162float(h1));
                    *(uint32_t*)(C1 + (size_t)row * N + col) = u1;
                    *(uint32_t*)(C2 + (size_t)row * N + col) = u2;
                }
            }
        }
    }
}

// ---------------- attention: HMMA bf16x3, causal decay mask -----------------
// block: 128 q-rows of one (b,h); 8 warps x 16 rows. t-tiles of 64 rows,
// K/V double-buffered. S stays in registers. Epilogue fuses LN+SiLU+split.
#define AT_LDB    144                        // smem row stride (bytes)
#define AT_Q1     0
#define AT_Q2     (128*AT_LDB)               // 18432
#define AT_STAGE0 (2*128*AT_LDB)             // 36864
#define AT_KTILE  (64*AT_LDB)                // 9216
#define AT_STAGE_SZ (4*AT_KTILE)             // 36864
#define ATTN_SMEM (AT_STAGE0 + 2*AT_STAGE_SZ)  // 110592

__global__ __launch_bounds__(256)
void attn_mma_kernel(const float* __restrict__ lnw, const float* __restrict__ lnb) {
    extern __shared__ char smc[];
    uint32_t smb = smem_u32(smc);
    int tid = threadIdx.x, lane = tid & 31, wid = tid >> 5;
    int qb = (int)(gridDim.x - 1 - blockIdx.x);   // heavy blocks first
    int h = blockIdx.y, bb = blockIdx.z;
    int q0 = qb * 128;
    size_t rowbase = (size_t)bb * NS;
    size_t headoff = (size_t)h * HD;
    float dec = (float)log(1.0 - exp2(-5.0 - (double)h));   // negative

    // ---- load Q tile (both splits) ----
#pragma unroll
    for (int it = 0; it < 8; it++) {
        int idx = tid + it*256;               // 0..2047
        int t  = idx >> 10;                   // 0:q1 1:q2
        int rr = (idx >> 3) & 127;
        int cc = idx & 7;
        const __nv_bfloat16* src = (t ? g_q2 : g_q1) +
            (rowbase + q0 + rr)*ND + headoff + cc*8;
        uint32_t dst = smb + (t ? AT_Q2 : AT_Q1) + rr*AT_LDB + cc*16;
        CP16(dst, src);
    }

#define AT_LOAD(stage, t0_)                                                    \
    {                                                                          \
        uint32_t stb = smb + AT_STAGE0 + (stage)*AT_STAGE_SZ;                  \
        _Pragma("unroll")                                                      \
        for (int it = 0; it < 8; it++) {                                       \
            int idx = tid + it*256;                                            \
            int ts = idx >> 9;                                                 \
            int rr = (idx >> 3) & 63;                                          \
            int cc = idx & 7;                                                  \
            const __nv_bfloat16* sp =                                          \
                (ts==0 ? g_k1 : ts==1 ? g_k2 : ts==2 ? g_v1 : g_v2) +          \
                (rowbase + (t0_) + rr)*ND + headoff + cc*8;                    \
            CP16(stb + ts*AT_KTILE + rr*AT_LDB + cc*16, sp);                   \
        }                                                                      \
        asm volatile("cp.async.commit_group;");                                \
    }

    AT_LOAD(0, 0)
    asm volatile("cp.async.wait_group 0;");
    __syncthreads();

    int wr = wid * 16;
    int qlo = lane >> 2;                      // 0..7 row within 8
    uint32_t aoff = (uint32_t)((wr + (lane & 7) + 8*((lane >> 3) & 1))*AT_LDB
                               + 16*(lane >> 4));
    uint32_t boff = (uint32_t)(((lane & 7) + 8*((lane >> 3) >> 1))*AT_LDB
                               + 16*((lane >> 3) & 1));
    uint32_t voff = (uint32_t)((lane & 15)*AT_LDB + 16*(lane >> 4));

    float oacc[8][4] = {};
    float mul8 = __expf(dec * 8.0f);
    int ntt = 2*qb + 2;

    for (int tt = 0; tt < ntt; tt++) {
        int t0 = tt * 64;
        if (tt + 1 < ntt) AT_LOAD((tt+1) & 1, (tt+1)*64)

        uint32_t stb = smb + AT_STAGE0 + (tt & 1)*AT_STAGE_SZ;
        bool active = (q0 + wr + 15) >= t0;
        if (active) {
            // ---- S = Q K^T (bf16x3) ----
            float s[8][4] = {};
#pragma unroll
            for (int kk = 0; kk < 4; kk++) {
                uint32_t a1f[4], a2f[4];
                LDSM4(a1f, smb + AT_Q1 + aoff + kk*32);
                LDSM4(a2f, smb + AT_Q2 + aoff + kk*32);
#pragma unroll
                for (int nc = 0; nc < 4; nc++) {
                    uint32_t f1[4], f2[4];
                    LDSM4(f1, stb + boff + nc*16*AT_LDB + kk*32);
                    LDSM4(f2, stb + AT_KTILE + boff + nc*16*AT_LDB + kk*32);
                    MMA16816(s[2*nc],   a1f, f1[0], f1[1]);
                    MMA16816(s[2*nc+1], a1f, f1[2], f1[3]);
                    MMA16816(s[2*nc],   a2f, f1[0], f1[1]);
                    MMA16816(s[2*nc+1], a2f, f1[2], f1[3]);
                    MMA16816(s[2*nc],   a1f, f2[0], f2[1]);
                    MMA16816(s[2*nc+1], a1f, f2[2], f2[3]);
                }
            }
            // ---- decay mask (factored) + causal ----
            float rowf0 = __expf(dec * (float)(q0 + wr + qlo - t0));
            float rowf1 = rowf0 * mul8;
            float colf[8][2];
#pragma unroll
            for (int nt = 0; nt < 8; nt++)
#pragma unroll
                for (int par = 0; par < 2; par++)
                    colf[nt][par] = __expf(-dec * (float)(nt*8 + (lane&3)*2 + par));
            bool needcmp = (q0 + wr) < (t0 + 63);
#pragma unroll
            for (int nt = 0; nt < 8; nt++)
#pragma unroll
                for (int e = 0; e < 4; e++) {
                    int rloc = qlo + ((e >= 2) ? 8 : 0);
                    int cloc = nt*8 + (lane&3)*2 + (e & 1);
                    float m = ((e >= 2) ? rowf1 : rowf0) * colf[nt][e & 1];
                    if (needcmp && (q0 + wr + rloc) < (t0 + cloc)) m = 0.f;
                    s[nt][e] *= m;
                }
            // ---- split S in-register, O += S V (bf16x3) ----
#pragma unroll
            for (int kt = 0; kt < 4; kt++) {
                uint32_t sp1[4], sp2[4];
#pragma unroll
                for (int j = 0; j < 4; j++) {
                    int nt = 2*kt + (j >> 1);
                    int e0 = (j & 1) * 2;
                    float x0 = s[nt][e0], x1 = s[nt][e0+1];
                    __nv_bfloat16 h0 = __float2bfloat16(x0), h1 = __float2bfloat16(x1);
                    sp1[j] = (uint32_t)__bfloat16_as_ushort(h0) |
                             ((uint32_t)__bfloat16_as_ushort(h1) << 16);
                    sp2[j] = packbf2(x0 - __bfloat162float(h0),
                                     x1 - __bfloat162float(h1));
                }
#pragma unroll
                for (int nv = 0; nv < 4; nv++) {
                    uint32_t f1[4], f2[4];
                    LDSM4T(f1, stb + 2*AT_KTILE + voff + kt*16*AT_LDB + nv*32);
                    LDSM4T(f2, stb + 3*AT_KTILE + voff + kt*16*AT_LDB + nv*32);
                    MMA16816(oacc[2*nv],   sp1, f1[0], f1[1]);
                    MMA16816(oacc[2*nv+1], sp1, f1[2], f1[3]);
                    MMA16816(oacc[2*nv],   sp2, f1[0], f1[1]);
                    MMA16816(oacc[2*nv+1], sp2, f1[2], f1[3]);
                    MMA16816(oacc[2*nv],   sp1, f2[0], f2[1]);
                    MMA16816(oacc[2*nv+1], sp1, f2[2], f2[3]);
                }
            }
        }
        if (tt + 1 < ntt) asm volatile("cp.async.wait_group 0;");
        __syncthreads();
    }

    // ---- fused LayerNorm(64) + SiLU + bf16 split, write to g_a1/g_a2 ----
    int colbase = (lane & 3)*2;
#pragma unroll
    for (int half = 0; half < 2; half++) {
        float sum = 0.f, sq = 0.f;
#pragma unroll
        for (int nt = 0; nt < 8; nt++) {
            float v0 = oacc[nt][half*2], v1 = oacc[nt][half*2+1];
            sum += v0 + v1;
            sq  += v0*v0 + v1*v1;
        }
        sum += __shfl_xor_sync(0xffffffffu, sum, 1);
        sq  += __shfl_xor_sync(0xffffffffu, sq, 1);
        sum += __shfl_xor_sync(0xffffffffu, sum, 2);
        sq  += __shfl_xor_sync(0xffffffffu, sq, 2);
        float mean = sum * (1.f/64.f);
        float var  = sq * (1.f/64.f) - mean*mean;
        float rs = rsqrtf(var + 1e-5f);
        size_t rbase = (rowbase + q0 + wr + qlo + half*8)*ND + headoff;
#pragma unroll
        for (int nt = 0; nt < 8; nt++) {
            int c = nt*8 + colbase;
            float y0 = (oacc[nt][half*2]   - mean)*rs*lnw[c]   + lnb[c];
            float y1 = (oacc[nt][half*2+1] - mean)*rs*lnw[c+1] + lnb[c+1];
            y0 = y0 / (1.f + __expf(-y0));
            y1 = y1 / (1.f + __expf(-y1));
            __nv_bfloat16 h0 = __float2bfloat16(y0), h1 = __float2bfloat16(y1);
            uint32_t u1 = (uint32_t)__bfloat16_as_ushort(h0) |
                          ((uint32_t)__bfloat16_as_ushort(h1) << 16);
            uint32_t u2 = packbf2(y0 - __bfloat162float(h0),
                                  y1 - __bfloat162float(h1));
            *(uint32_t*)(g_a1 + rbase + c) = u1;
            *(uint32_t*)(g_a2 + rbase + c) = u2;
        }
    }
}

// ---------------- launcher ---------------------------------------------------
extern "C" void kernel_launch(void* const* d_in, const int* in_sizes, int n_in,
                              void* d_out, int out_size) {
    const float* x   = (const float*)d_in[0];
    const float* Wq  = (const float*)d_in[1];
    const float* Wk  = (const float*)d_in[2];
    const float* Wv  = (const float*)d_in[3];
    const float* Wo  = (const float*)d_in[4];
    const float* lnw = (const float*)d_in[5];
    const float* lnb = (const float*)d_in[6];
    float* out = (float*)d_out;

    __nv_bfloat16 *a1, *a2, *b1, *b2;
    cudaGetSymbolAddress((void**)&a1, g_a1);
    cudaGetSymbolAddress((void**)&a2, g_a2);
    cudaGetSymbolAddress((void**)&b1, g_b1);
    cudaGetSymbolAddress((void**)&b2, g_b2);

    trig_kernel<<<(NS*(HD/2)+255)/256, 256>>>();

    cudaFuncSetAttribute(gemm_mma<0>, cudaFuncAttributeMaxDynamicSharedMemorySize, GEMM_DYNSMEM);
    cudaFuncSetAttribute(gemm_mma<3>, cudaFuncAttributeMaxDynamicSharedMemorySize, GEMM_DYNSMEM);
    cudaFuncSetAttribute(attn_mma_kernel, cudaFuncAttributeMaxDynamicSharedMemorySize, ATTN_SMEM);

    dim3 wsplit((ND*ND/4 + 255)/256);
    dim3 asplit(((size_t)NM*ND/4 + 255)/256);

    // split activations (x) and all three weights
    split_kernel<<<asplit, 256>>>(x, a1, a2, NM*ND);
    split3_kernel<<<dim3(ND*ND/4/256, 3), 256>>>(Wq, Wk, Wv);

    // fused QKV projection: one launch, grid.z selects weight + output (+RoPE)
    gemm_mma<3><<<dim3(ND/128, NM/128, 3), 256, GEMM_DYNSMEM>>>(
        a1, a2, b1, b2, nullptr, NM, ND, ND);

    // attention writes LN(SiLU(O)) bf16 splits directly into g_a1/g_a2
    attn_mma_kernel<<<dim3(NS/128, NH, NB), 256, ATTN_SMEM>>>(lnw, lnb);

    split_kernel<<<wsplit, 256>>>(Wo, b1, b2, ND*ND);
    gemm_mma<0><<<dim3(ND/128, NM/128), 256, GEMM_DYNSMEM>>>(
        a1, a2, b1, b2, out, NM, ND, ND);
}